// round 7
// baseline (speedup 1.0000x reference)
#include <cuda_runtime.h>
#include <cuda_bf16.h>
#include <cuda_fp8.h>
#include <math.h>
#include <stdint.h>

#define D 2048
#define NA 64
#define BATCH 64
#define ROWS (BATCH * NA)        // 4096
#define LN_EPS 1e-5f
#define ID_PRESERVE 0.1f
#define SIGNAL_BOUND 1.0f
#define SINKHORN_ITERS 50

// GEMM: CTA 128x128, 3-stage cp.async. 64 iters: 32 fp8 (corrections) + 32 bf16 (hh)
#define GBM 128
#define GBN 128
#define KIT_TOTAL 64
#define GSTAGES 3
#define GSTAGE_BYTES 32768       // A 16KB + B 16KB (128 rows x 128B each)

#define SCORE_KSPLIT 4
#define SCORE_KCHUNK (D / SCORE_KSPLIT)   // 512

#define CORR_SCALE 256.0f
#define CORR_INV  0.00390625f

// ---------------- scratch (device globals; no allocation allowed) ----------
__device__ float g_normed[ROWS * D];
__device__ float g_q[ROWS * D];
__device__ float g_k[ROWS * D];
__device__ float g_v[ROWS * D];
__device__ float g_mixed[ROWS * D];
__device__ float g_spart[SCORE_KSPLIT * BATCH * NA * NA];
__device__ float g_attn[BATCH * NA * NA];
// hi-only bf16 operands (for hh pass): row stride 2048 elems = 4096 B
__device__ __nv_bfloat16 g_A2h[(size_t)ROWS * D];
__device__ __nv_bfloat16 g_W2h[3ull * D * D];
// fp8 correction operands: row = [hi e4m3 (2048 B) | lo*256 e4m3 (2048 B)] for A,
//                          row = [lo*256 (2048 B) | hi (2048 B)] for W
__device__ uint8_t g_A8[(size_t)ROWS * 2 * D];
__device__ uint8_t g_W8[3ull * D * 2 * D];

// ---------------- PTX helpers ------------------------------------------------
__device__ __forceinline__ uint32_t smem_u32(const void* p) {
    uint32_t a;
    asm("{ .reg .u64 t; cvta.to.shared.u64 t, %1; cvt.u32.u64 %0, t; }" : "=r"(a) : "l"(p));
    return a;
}
__device__ __forceinline__ void cp16(uint32_t dst, const void* src) {
    asm volatile("cp.async.cg.shared.global [%0], [%1], 16;" :: "r"(dst), "l"(src));
}
__device__ __forceinline__ void cp_commit() { asm volatile("cp.async.commit_group;" ::: "memory"); }
template <int N>
__device__ __forceinline__ void cp_wait() { asm volatile("cp.async.wait_group %0;" :: "n"(N) : "memory"); }

#define LDSM4(r0, r1, r2, r3, addr) \
    asm volatile("ldmatrix.sync.aligned.m8n8.x4.shared.b16 {%0,%1,%2,%3}, [%4];" \
                 : "=r"(r0), "=r"(r1), "=r"(r2), "=r"(r3) : "r"(addr))

// ---------------- conversion helpers -----------------------------------------
__device__ __forceinline__ uint32_t fp8x4(float a, float b, float c, float d) {
    uint32_t r0 = __nv_cvt_float_to_fp8(a, __NV_SATFINITE, __NV_E4M3);
    uint32_t r1 = __nv_cvt_float_to_fp8(b, __NV_SATFINITE, __NV_E4M3);
    uint32_t r2 = __nv_cvt_float_to_fp8(c, __NV_SATFINITE, __NV_E4M3);
    uint32_t r3 = __nv_cvt_float_to_fp8(d, __NV_SATFINITE, __NV_E4M3);
    return r0 | (r1 << 8) | (r2 << 16) | (r3 << 24);
}
// hi = packed bf16 of v; lo = exact float residual v - float(hi)
__device__ __forceinline__ void splitf(float4 v, uint2& hi, float4& lo) {
    __nv_bfloat16 hx = __float2bfloat16(v.x);
    __nv_bfloat16 hy = __float2bfloat16(v.y);
    __nv_bfloat16 hz = __float2bfloat16(v.z);
    __nv_bfloat16 hw = __float2bfloat16(v.w);
    lo.x = v.x - __bfloat162float(hx);
    lo.y = v.y - __bfloat162float(hy);
    lo.z = v.z - __bfloat162float(hz);
    lo.w = v.w - __bfloat162float(hw);
    union { __nv_bfloat16 h[4]; uint2 u; } a;
    a.h[0] = hx; a.h[1] = hy; a.h[2] = hz; a.h[3] = hw;
    hi = a.u;
}

// ---------------- LayerNorm + emit bf16-hi and fp8 operands ------------------
__global__ __launch_bounds__(256) void ln_kernel(const float* __restrict__ x,
                                                 const float* __restrict__ w,
                                                 const float* __restrict__ b) {
    __shared__ float redS[8], redQ[8];
    int row = blockIdx.x;
    int tid = threadIdx.x;
    const float4* xr = (const float4*)(x + (size_t)row * D);
    float4 v0 = xr[tid];
    float4 v1 = xr[tid + 256];
    float s  = v0.x + v0.y + v0.z + v0.w + v1.x + v1.y + v1.z + v1.w;
    float ss = v0.x*v0.x + v0.y*v0.y + v0.z*v0.z + v0.w*v0.w
             + v1.x*v1.x + v1.y*v1.y + v1.z*v1.z + v1.w*v1.w;
    #pragma unroll
    for (int o = 16; o; o >>= 1) {
        s  += __shfl_xor_sync(0xFFFFFFFFu, s, o);
        ss += __shfl_xor_sync(0xFFFFFFFFu, ss, o);
    }
    int wid = tid >> 5;
    if ((tid & 31) == 0) { redS[wid] = s; redQ[wid] = ss; }
    __syncthreads();
    float ts = 0.f, tq = 0.f;
    #pragma unroll
    for (int i = 0; i < 8; i++) { ts += redS[i]; tq += redQ[i]; }
    float mean = ts * (1.0f / D);
    float var  = tq * (1.0f / D) - mean * mean;
    float r = 1.0f / sqrtf(var + LN_EPS);

    const float4* wr = (const float4*)w;
    const float4* br = (const float4*)b;
    float4 w0 = wr[tid], w1 = wr[tid + 256];
    float4 b0 = br[tid], b1 = br[tid + 256];
    float4 o0, o1;
    o0.x = (v0.x - mean) * r * w0.x + b0.x;
    o0.y = (v0.y - mean) * r * w0.y + b0.y;
    o0.z = (v0.z - mean) * r * w0.z + b0.z;
    o0.w = (v0.w - mean) * r * w0.w + b0.w;
    o1.x = (v1.x - mean) * r * w1.x + b1.x;
    o1.y = (v1.y - mean) * r * w1.y + b1.y;
    o1.z = (v1.z - mean) * r * w1.z + b1.z;
    o1.w = (v1.w - mean) * r * w1.w + b1.w;
    float4* outr = (float4*)(g_normed + (size_t)row * D);
    outr[tid] = o0;
    outr[tid + 256] = o1;

    uint2 h0, h1; float4 l0, l1;
    splitf(o0, h0, l0);
    splitf(o1, h1, l1);
    // bf16 hi
    __nv_bfloat16* ah = g_A2h + (size_t)row * D;
    ((uint2*)ah)[tid] = h0;
    ((uint2*)ah)[tid + 256] = h1;
    // fp8: [hi | lo*256]
    uint8_t* a8 = g_A8 + (size_t)row * (2 * D);
    ((uint32_t*)a8)[tid]       = fp8x4(o0.x, o0.y, o0.z, o0.w);
    ((uint32_t*)a8)[tid + 256] = fp8x4(o1.x, o1.y, o1.z, o1.w);
    ((uint32_t*)(a8 + D))[tid]       = fp8x4(l0.x * CORR_SCALE, l0.y * CORR_SCALE, l0.z * CORR_SCALE, l0.w * CORR_SCALE);
    ((uint32_t*)(a8 + D))[tid + 256] = fp8x4(l1.x * CORR_SCALE, l1.y * CORR_SCALE, l1.z * CORR_SCALE, l1.w * CORR_SCALE);
}

// ---------------- weight convert: W2h (hi bf16) + W8 ([lo*256 | hi] e4m3) ---
__global__ __launch_bounds__(256) void conv_w_kernel(const float* __restrict__ wq,
                                                     const float* __restrict__ wk,
                                                     const float* __restrict__ wv) {
    int j = blockIdx.x;                    // weight row (output feature)
    int wsel = blockIdx.y;                 // 0..2
    const float* W = (wsel == 0) ? wq : (wsel == 1) ? wk : wv;
    __nv_bfloat16* dh = g_W2h + (size_t)wsel * ((size_t)D * D) + (size_t)j * D;
    uint8_t* d8 = g_W8 + (size_t)wsel * ((size_t)D * 2 * D) + (size_t)j * (2 * D);
    const float4* src = (const float4*)(W + (size_t)j * D);
    int tid = threadIdx.x;
    #pragma unroll
    for (int h = 0; h < 2; h++) {
        float4 v = src[tid + h * 256];
        uint2 hi; float4 lo;
        splitf(v, hi, lo);
        ((uint2*)dh)[tid + h * 256] = hi;
        // W8 layout: [lo*256 | hi]
        ((uint32_t*)d8)[tid + h * 256]       = fp8x4(lo.x * CORR_SCALE, lo.y * CORR_SCALE, lo.z * CORR_SCALE, lo.w * CORR_SCALE);
        ((uint32_t*)(d8 + D))[tid + h * 256] = fp8x4(v.x, v.y, v.z, v.w);
    }
}

// ---------------- QKV GEMM: fp8 corrections then bf16 hh ---------------------
// C[4096, 2048] = A @ W^T:  iters 0..31 e4m3 K=4096 (-> 2^8*(hl+lh)),
// scale by 2^-8, iters 32..63 bf16 K=2048 (hh).
__global__ __launch_bounds__(256, 2) void qkv_mma_kernel(const float* __restrict__ bq,
                                                         const float* __restrict__ bk,
                                                         const float* __restrict__ bv) {
    extern __shared__ __align__(128) char sm[];
    uint32_t sbase = smem_u32(sm);

    int tid = threadIdx.x;
    int lane = tid & 31;
    int wid = tid >> 5;
    int warp_m = wid >> 2;        // 0..1  -> 64-row slab
    int warp_n = wid & 3;         // 0..3  -> 32-col slab
    int bx = blockIdx.x;          // N tile
    int by = blockIdx.y;          // M tile
    int bz = blockIdx.z;          // q/k/v

    const float* bias = (bz == 0) ? bq : (bz == 1) ? bk : bv;
    float* C = (bz == 0) ? g_q : (bz == 1) ? g_k : g_v;
    const char* A8b = (const char*)g_A8;                                   // stride 4096 B
    const char* W8b = (const char*)g_W8 + (size_t)bz * ((size_t)D * 2 * D); // stride 4096 B
    const char* Ahb = (const char*)g_A2h;                                  // stride 4096 B
    const char* Whb = (const char*)g_W2h + (size_t)bz * ((size_t)D * D) * 2; // stride 4096 B

    auto load_stage = [&](int st, int j) {
        size_t koff = (size_t)(j & 31) * 128;
        const char* Asrc = (j < 32) ? A8b : Ahb;
        const char* Bsrc = (j < 32) ? W8b : Whb;
        uint32_t sA = sbase + st * GSTAGE_BYTES;
        uint32_t sB = sA + 16384;
        #pragma unroll
        for (int i = 0; i < 4; i++) {
            int idx = tid + i * 256;
            int row = idx >> 3;
            int c16 = idx & 7;
            uint32_t dst = sA + row * 128 + ((c16 ^ (row & 7)) << 4);
            cp16(dst, Asrc + (size_t)(by * GBM + row) * 4096 + koff + c16 * 16);
        }
        #pragma unroll
        for (int i = 0; i < 4; i++) {
            int idx = tid + i * 256;
            int row = idx >> 3;
            int c16 = idx & 7;
            uint32_t dst = sB + row * 128 + ((c16 ^ (row & 7)) << 4);
            cp16(dst, Bsrc + (size_t)(bx * GBN + row) * 4096 + koff + c16 * 16);
        }
    };

    float acc[4][4][4];
    #pragma unroll
    for (int mf = 0; mf < 4; mf++)
        #pragma unroll
        for (int nf = 0; nf < 4; nf++)
            #pragma unroll
            for (int q = 0; q < 4; q++) acc[mf][nf][q] = 0.f;

    load_stage(0, 0);
    cp_commit();
    load_stage(1, 1);
    cp_commit();

    int arow_off = warp_m * 64 + (lane & 15);
    int brow_off = warp_n * 32 + (lane & 15);
    int khalf = lane >> 4;
    int swz_x = lane & 7;

    for (int it = 0; it < KIT_TOTAL; it++) {
        cp_wait<1>();
        __syncthreads();
        if (it + 2 < KIT_TOTAL) load_stage((it + 2) % GSTAGES, it + 2);
        cp_commit();

        if (it == 32) {
            // corrections complete: fold 2^-8 scale before accumulating hh
            #pragma unroll
            for (int mf = 0; mf < 4; mf++)
                #pragma unroll
                for (int nf = 0; nf < 4; nf++)
                    #pragma unroll
                    for (int q = 0; q < 4; q++) acc[mf][nf][q] *= CORR_INV;
        }

        uint32_t sA = sbase + (it % GSTAGES) * GSTAGE_BYTES;
        uint32_t sB = sA + 16384;
        bool f8 = (it < 32);

        #pragma unroll
        for (int ks = 0; ks < 4; ks++) {
            uint32_t swz = (uint32_t)(((ks * 2 + khalf) ^ swz_x) << 4);
            uint32_t a[4][4];
            uint32_t bf[4][2];
            #pragma unroll
            for (int mf = 0; mf < 4; mf++) {
                uint32_t addr = sA + (uint32_t)(arow_off + mf * 16) * 128 + swz;
                LDSM4(a[mf][0], a[mf][1], a[mf][2], a[mf][3], addr);
            }
            #pragma unroll
            for (int nf2 = 0; nf2 < 2; nf2++) {
                uint32_t r0, r1, r2, r3;
                uint32_t addr = sB + (uint32_t)(brow_off + nf2 * 16) * 128 + swz;
                LDSM4(r0, r1, r2, r3, addr);
                bf[nf2 * 2 + 0][0] = r0; bf[nf2 * 2 + 1][0] = r1;
                bf[nf2 * 2 + 0][1] = r2; bf[nf2 * 2 + 1][1] = r3;
            }
            if (f8) {
                #pragma unroll
                for (int mf = 0; mf < 4; mf++)
                    #pragma unroll
                    for (int nf = 0; nf < 4; nf++)
                        asm volatile(
                            "mma.sync.aligned.m16n8k32.row.col.f32.e4m3.e4m3.f32 "
                            "{%0,%1,%2,%3}, {%4,%5,%6,%7}, {%8,%9}, {%0,%1,%2,%3};"
                            : "+f"(acc[mf][nf][0]), "+f"(acc[mf][nf][1]),
                              "+f"(acc[mf][nf][2]), "+f"(acc[mf][nf][3])
                            : "r"(a[mf][0]), "r"(a[mf][1]), "r"(a[mf][2]), "r"(a[mf][3]),
                              "r"(bf[nf][0]), "r"(bf[nf][1]));
            } else {
                #pragma unroll
                for (int mf = 0; mf < 4; mf++)
                    #pragma unroll
                    for (int nf = 0; nf < 4; nf++)
                        asm volatile(
                            "mma.sync.aligned.m16n8k16.row.col.f32.bf16.bf16.f32 "
                            "{%0,%1,%2,%3}, {%4,%5,%6,%7}, {%8,%9}, {%0,%1,%2,%3};"
                            : "+f"(acc[mf][nf][0]), "+f"(acc[mf][nf][1]),
                              "+f"(acc[mf][nf][2]), "+f"(acc[mf][nf][3])
                            : "r"(a[mf][0]), "r"(a[mf][1]), "r"(a[mf][2]), "r"(a[mf][3]),
                              "r"(bf[nf][0]), "r"(bf[nf][1]));
            }
        }
        __syncthreads();
    }

    // epilogue: direct stores with bias
    int row_base = by * GBM + warp_m * 64 + (lane >> 2);
    int col_base = bx * GBN + warp_n * 32 + 2 * (lane & 3);
    #pragma unroll
    for (int nf = 0; nf < 4; nf++) {
        int c = col_base + nf * 8;
        float b0 = bias[c], b1 = bias[c + 1];
        #pragma unroll
        for (int mf = 0; mf < 4; mf++) {
            int r0 = row_base + mf * 16;
            float2 v0 = make_float2(acc[mf][nf][0] + b0, acc[mf][nf][1] + b1);
            float2 v1 = make_float2(acc[mf][nf][2] + b0, acc[mf][nf][3] + b1);
            *(float2*)(C + (size_t)r0 * D + c) = v0;
            *(float2*)(C + (size_t)(r0 + 8) * D + c) = v1;
        }
    }
}

// ---------------- scores partial: S_part[ks][b] = q.k over K chunk ----------
__global__ __launch_bounds__(256) void scores_kernel() {
    int ks = blockIdx.x;
    int b = blockIdx.y;
    const float* Qb = g_q + (size_t)b * NA * D + (size_t)ks * SCORE_KCHUNK;
    const float* Kb = g_k + (size_t)b * NA * D + (size_t)ks * SCORE_KCHUNK;
    __shared__ float Qs[32][68];
    __shared__ float Ks[32][68];
    int tid = threadIdx.x;
    int lr = tid >> 3;
    int lk = (tid & 7) << 2;
    int tm = tid >> 4, tn = tid & 15;
    float acc[4][4];
    #pragma unroll
    for (int i = 0; i < 4; i++)
        #pragma unroll
        for (int j = 0; j < 4; j++) acc[i][j] = 0.f;

    for (int k0 = 0; k0 < SCORE_KCHUNK; k0 += 32) {
        float4 q0 = *(const float4*)(Qb + (size_t)lr * D + k0 + lk);
        float4 q1 = *(const float4*)(Qb + (size_t)(lr + 32) * D + k0 + lk);
        float4 c0 = *(const float4*)(Kb + (size_t)lr * D + k0 + lk);
        float4 c1 = *(const float4*)(Kb + (size_t)(lr + 32) * D + k0 + lk);
        __syncthreads();
        Qs[lk + 0][lr] = q0.x; Qs[lk + 1][lr] = q0.y; Qs[lk + 2][lr] = q0.z; Qs[lk + 3][lr] = q0.w;
        Qs[lk + 0][lr + 32] = q1.x; Qs[lk + 1][lr + 32] = q1.y; Qs[lk + 2][lr + 32] = q1.z; Qs[lk + 3][lr + 32] = q1.w;
        Ks[lk + 0][lr] = c0.x; Ks[lk + 1][lr] = c0.y; Ks[lk + 2][lr] = c0.z; Ks[lk + 3][lr] = c0.w;
        Ks[lk + 0][lr + 32] = c1.x; Ks[lk + 1][lr + 32] = c1.y; Ks[lk + 2][lr + 32] = c1.z; Ks[lk + 3][lr + 32] = c1.w;
        __syncthreads();
        #pragma unroll
        for (int kk = 0; kk < 32; kk++) {
            float a[4], c[4];
            *(float4*)a = *(const float4*)(&Qs[kk][tm * 4]);
            *(float4*)c = *(const float4*)(&Ks[kk][tn * 4]);
            #pragma unroll
            for (int i = 0; i < 4; i++)
                #pragma unroll
                for (int j = 0; j < 4; j++)
                    acc[i][j] += a[i] * c[j];
        }
    }
    float* dst = g_spart + ((size_t)ks * BATCH + b) * 4096;
    #pragma unroll
    for (int i = 0; i < 4; i++)
        #pragma unroll
        for (int j = 0; j < 4; j++)
            dst[(tm * 4 + i) * 64 + (tn * 4 + j)] = acc[i][j];
}

// ---------------- Sinkhorn (sums partials, applies 1/sqrt(D)) ---------------
__global__ __launch_bounds__(1024) void sinkhorn_kernel(float* __restrict__ attn_out) {
    int b = blockIdx.x;
    __shared__ float m[64][65];
    int tid = threadIdx.x;
    const float invS = 1.0f / 45.254833995939045f;
    const float* p0 = g_spart + (size_t)b * 4096;
    const size_t pstride = (size_t)BATCH * 4096;
    for (int i = tid; i < 4096; i += 1024) {
        float v = p0[i] + p0[i + pstride] + p0[i + 2 * pstride] + p0[i + 3 * pstride];
        m[i >> 6][i & 63] = v * invS;
    }
    __syncthreads();
    int w = tid >> 5, lane = tid & 31;
    for (int it = 0; it < SINKHORN_ITERS; it++) {
        #pragma unroll
        for (int rr = 0; rr < 2; rr++) {
            int r = w * 2 + rr;
            float x0 = m[r][lane], x1 = m[r][lane + 32];
            float mx = fmaxf(x0, x1);
            #pragma unroll
            for (int o = 16; o; o >>= 1) mx = fmaxf(mx, __shfl_xor_sync(0xFFFFFFFFu, mx, o));
            float s = expf(x0 - mx) + expf(x1 - mx);
            #pragma unroll
            for (int o = 16; o; o >>= 1) s += __shfl_xor_sync(0xFFFFFFFFu, s, o);
            float lse = mx + logf(s);
            m[r][lane] = x0 - lse;
            m[r][lane + 32] = x1 - lse;
        }
        __syncthreads();
        #pragma unroll
        for (int cc = 0; cc < 2; cc++) {
            int c = w * 2 + cc;
            float x0 = m[lane][c], x1 = m[lane + 32][c];
            float mx = fmaxf(x0, x1);
            #pragma unroll
            for (int o = 16; o; o >>= 1) mx = fmaxf(mx, __shfl_xor_sync(0xFFFFFFFFu, mx, o));
            float s = expf(x0 - mx) + expf(x1 - mx);
            #pragma unroll
            for (int o = 16; o; o >>= 1) s += __shfl_xor_sync(0xFFFFFFFFu, s, o);
            float lse = mx + logf(s);
            m[lane][c] = x0 - lse;
            m[lane + 32][c] = x1 - lse;
        }
        __syncthreads();
    }
    for (int i = tid; i < 4096; i += 1024) {
        float e = expf(m[i >> 6][i & 63]);
        g_attn[(size_t)b * 4096 + i] = e;
        if (attn_out) attn_out[(size_t)b * 4096 + i] = e;
    }
}

// ---------------- attended = attn @ V, fused mix ----------------------------
__global__ __launch_bounds__(256) void attended_kernel() {
    int d0 = blockIdx.x * 128;
    int b = blockIdx.y;
    __shared__ float attn_s[64][64];
    __shared__ float4 Vs[64][32];
    int tid = threadIdx.x;
    const float* ab = g_attn + (size_t)b * 4096;
    for (int i = tid; i < 4096; i += 256) attn_s[i >> 6][i & 63] = ab[i];
    const float* Vb = g_v + (size_t)b * NA * D;
    {
        int r = tid >> 5;
        int c = tid & 31;
        #pragma unroll
        for (int p = 0; p < 8; p++)
            Vs[r + p * 8][c] = *(const float4*)(Vb + (size_t)(r + p * 8) * D + d0 + c * 4);
    }
    __syncthreads();
    int tx = tid & 31, ty = tid >> 5;
    float4 acc[8];
    #pragma unroll
    for (int i = 0; i < 8; i++) acc[i] = make_float4(0.f, 0.f, 0.f, 0.f);
    for (int mm = 0; mm < 64; mm++) {
        float4 v4 = Vs[mm][tx];
        #pragma unroll
        for (int i = 0; i < 8; i++) {
            float a = attn_s[ty * 8 + i][mm];
            acc[i].x += a * v4.x;
            acc[i].y += a * v4.y;
            acc[i].z += a * v4.z;
            acc[i].w += a * v4.w;
        }
    }
    #pragma unroll
    for (int i = 0; i < 8; i++) {
        int n = ty * 8 + i;
        size_t off = ((size_t)(b * 64 + n)) * D + d0 + tx * 4;
        float4 nm = *(const float4*)(g_normed + off);
        float4 o;
        o.x = ID_PRESERVE * nm.x + (1.0f - ID_PRESERVE) * acc[i].x;
        o.y = ID_PRESERVE * nm.y + (1.0f - ID_PRESERVE) * acc[i].y;
        o.z = ID_PRESERVE * nm.z + (1.0f - ID_PRESERVE) * acc[i].z;
        o.w = ID_PRESERVE * nm.w + (1.0f - ID_PRESERVE) * acc[i].w;
        *(float4*)(g_mixed + off) = o;
    }
}

// ---------------- epilogue ---------------------------------------------------
__global__ __launch_bounds__(256) void epilogue_kernel(const float* __restrict__ x,
                                                       const float* __restrict__ biases,
                                                       const float* __restrict__ scales,
                                                       float* __restrict__ out) {
    __shared__ float red[8];
    int row = blockIdx.x;
    int n = row & 63;
    int tid = threadIdx.x;
    float sc = scales[n];
    const float4* mr = (const float4*)(g_mixed + (size_t)row * D);
    const float4* br = (const float4*)(biases + (size_t)n * D);
    float4 m0 = mr[tid], m1 = mr[tid + 256];
    float4 b0 = br[tid], b1 = br[tid + 256];
    float4 s0, s1;
    s0.x = (m0.x + b0.x) * sc; s0.y = (m0.y + b0.y) * sc;
    s0.z = (m0.z + b0.z) * sc; s0.w = (m0.w + b0.w) * sc;
    s1.x = (m1.x + b1.x) * sc; s1.y = (m1.y + b1.y) * sc;
    s1.z = (m1.z + b1.z) * sc; s1.w = (m1.w + b1.w) * sc;
    float ss = s0.x*s0.x + s0.y*s0.y + s0.z*s0.z + s0.w*s0.w
             + s1.x*s1.x + s1.y*s1.y + s1.z*s1.z + s1.w*s1.w;
    #pragma unroll
    for (int o = 16; o; o >>= 1) ss += __shfl_xor_sync(0xFFFFFFFFu, ss, o);
    if ((tid & 31) == 0) red[tid >> 5] = ss;
    __syncthreads();
    float tot = 0.f;
    #pragma unroll
    for (int i = 0; i < 8; i++) tot += red[i];
    float norm = sqrtf(tot);
    float inv = 1.0f / fmaxf(1.0f, norm / SIGNAL_BOUND);
    const float4* xr = (const float4*)(x + (size_t)row * D);
    float4 x0 = xr[tid], x1 = xr[tid + 256];
    float4 o0, o1;
    o0.x = x0.x + s0.x * inv; o0.y = x0.y + s0.y * inv;
    o0.z = x0.z + s0.z * inv; o0.w = x0.w + s0.w * inv;
    o1.x = x1.x + s1.x * inv; o1.y = x1.y + s1.y * inv;
    o1.z = x1.z + s1.z * inv; o1.w = x1.w + s1.w * inv;
    float4* outr = (float4*)(out + (size_t)row * D);
    outr[tid] = o0;
    outr[tid + 256] = o1;
}

// ---------------- launch -----------------------------------------------------
extern "C" void kernel_launch(void* const* d_in, const int* in_sizes, int n_in,
                              void* d_out, int out_size) {
    const float* agent_states  = (const float*)d_in[0];
    const float* ln_w          = (const float*)d_in[1];
    const float* ln_b          = (const float*)d_in[2];
    const float* wq            = (const float*)d_in[3];
    const float* bq            = (const float*)d_in[4];
    const float* wk            = (const float*)d_in[5];
    const float* bk            = (const float*)d_in[6];
    const float* wv            = (const float*)d_in[7];
    const float* bv            = (const float*)d_in[8];
    const float* agent_biases  = (const float*)d_in[9];
    const float* scale_factors = (const float*)d_in[10];
    float* out = (float*)d_out;
    float* attn_out = (out_size >= ROWS * D + BATCH * NA * NA) ? (out + (size_t)ROWS * D)
                                                               : nullptr;

    const int DYN_SMEM = GSTAGES * GSTAGE_BYTES;   // 96 KB
    cudaFuncSetAttribute(qkv_mma_kernel, cudaFuncAttributeMaxDynamicSharedMemorySize, DYN_SMEM);

    ln_kernel<<<ROWS, 256>>>(agent_states, ln_w, ln_b);
    conv_w_kernel<<<dim3(D, 3), 256>>>(wq, wk, wv);
    qkv_mma_kernel<<<dim3(D / GBN, ROWS / GBM, 3), 256, DYN_SMEM>>>(bq, bk, bv);
    scores_kernel<<<dim3(SCORE_KSPLIT, BATCH), 256>>>();
    sinkhorn_kernel<<<BATCH, 1024>>>(attn_out);
    attended_kernel<<<dim3(16, BATCH), 256>>>();
    epilogue_kernel<<<ROWS, 256>>>(agent_states, agent_biases, scale_factors, out);
}

// round 9
// speedup vs baseline: 1.4514x; 1.4514x over previous
#include <cuda_runtime.h>
#include <cuda_bf16.h>
#include <math.h>
#include <stdint.h>

#define D 2048
#define NA 64
#define BATCH 64
#define ROWS (BATCH * NA)        // 4096
#define LN_EPS 1e-5f
#define ID_PRESERVE 0.1f
#define SIGNAL_BOUND 1.0f
#define SINKHORN_ITERS 50

// GEMM: CTA 128x128, tf32 single pass K=2048, BK=32 fp32 (128B rows), 3-stage
#define GBM 128
#define GBN 128
#define KITERS 64                // 2048 / 32
#define GSTAGES 3
#define GSTAGE_BYTES 32768       // A 16KB + B 16KB (128 rows x 128B each)

#define SCORE_KSPLIT 4
#define SCORE_KCHUNK (D / SCORE_KSPLIT)   // 512

// ---------------- scratch (device globals; no allocation allowed) ----------
__device__ float g_normed[ROWS * D];
__device__ float g_q[ROWS * D];
__device__ float g_k[ROWS * D];
__device__ float g_v[ROWS * D];
__device__ float g_mixed[ROWS * D];
__device__ float g_spart[SCORE_KSPLIT * BATCH * NA * NA];
__device__ float g_attn[BATCH * NA * NA];
// tf32-rounded operands (stored as fp32 bit patterns)
__device__ float g_At[(size_t)ROWS * D];          // [4096, 2048]
__device__ float g_Wt[3ull * D * D];              // 3 x [2048, 2048]

// ---------------- PTX helpers ------------------------------------------------
__device__ __forceinline__ uint32_t smem_u32(const void* p) {
    uint32_t a;
    asm("{ .reg .u64 t; cvta.to.shared.u64 t, %1; cvt.u32.u64 %0, t; }" : "=r"(a) : "l"(p));
    return a;
}
__device__ __forceinline__ void cp16(uint32_t dst, const void* src) {
    asm volatile("cp.async.cg.shared.global [%0], [%1], 16;" :: "r"(dst), "l"(src));
}
__device__ __forceinline__ void cp_commit() { asm volatile("cp.async.commit_group;" ::: "memory"); }
template <int N>
__device__ __forceinline__ void cp_wait() { asm volatile("cp.async.wait_group %0;" :: "n"(N) : "memory"); }

#define LDSM4(r0, r1, r2, r3, addr) \
    asm volatile("ldmatrix.sync.aligned.m8n8.x4.shared.b16 {%0,%1,%2,%3}, [%4];" \
                 : "=r"(r0), "=r"(r1), "=r"(r2), "=r"(r3) : "r"(addr))

// tf32 round: cvt.rna.tf32.f32 requires a .b32 destination register
__device__ __forceinline__ float tf32r(float x) {
    uint32_t y;
    asm("cvt.rna.tf32.f32 %0, %1;" : "=r"(y) : "f"(x));
    return __uint_as_float(y);
}
__device__ __forceinline__ float4 tf32r4(float4 v) {
    return make_float4(tf32r(v.x), tf32r(v.y), tf32r(v.z), tf32r(v.w));
}

// ---------------- LayerNorm + emit tf32-rounded A ----------------------------
__global__ __launch_bounds__(256) void ln_kernel(const float* __restrict__ x,
                                                 const float* __restrict__ w,
                                                 const float* __restrict__ b) {
    __shared__ float redS[8], redQ[8];
    int row = blockIdx.x;
    int tid = threadIdx.x;
    const float4* xr = (const float4*)(x + (size_t)row * D);
    float4 v0 = xr[tid];
    float4 v1 = xr[tid + 256];
    float s  = v0.x + v0.y + v0.z + v0.w + v1.x + v1.y + v1.z + v1.w;
    float ss = v0.x*v0.x + v0.y*v0.y + v0.z*v0.z + v0.w*v0.w
             + v1.x*v1.x + v1.y*v1.y + v1.z*v1.z + v1.w*v1.w;
    #pragma unroll
    for (int o = 16; o; o >>= 1) {
        s  += __shfl_xor_sync(0xFFFFFFFFu, s, o);
        ss += __shfl_xor_sync(0xFFFFFFFFu, ss, o);
    }
    int wid = tid >> 5;
    if ((tid & 31) == 0) { redS[wid] = s; redQ[wid] = ss; }
    __syncthreads();
    float ts = 0.f, tq = 0.f;
    #pragma unroll
    for (int i = 0; i < 8; i++) { ts += redS[i]; tq += redQ[i]; }
    float mean = ts * (1.0f / D);
    float var  = tq * (1.0f / D) - mean * mean;
    float r = 1.0f / sqrtf(var + LN_EPS);

    const float4* wr = (const float4*)w;
    const float4* br = (const float4*)b;
    float4 w0 = wr[tid], w1 = wr[tid + 256];
    float4 b0 = br[tid], b1 = br[tid + 256];
    float4 o0, o1;
    o0.x = (v0.x - mean) * r * w0.x + b0.x;
    o0.y = (v0.y - mean) * r * w0.y + b0.y;
    o0.z = (v0.z - mean) * r * w0.z + b0.z;
    o0.w = (v0.w - mean) * r * w0.w + b0.w;
    o1.x = (v1.x - mean) * r * w1.x + b1.x;
    o1.y = (v1.y - mean) * r * w1.y + b1.y;
    o1.z = (v1.z - mean) * r * w1.z + b1.z;
    o1.w = (v1.w - mean) * r * w1.w + b1.w;
    float4* outr = (float4*)(g_normed + (size_t)row * D);
    outr[tid] = o0;
    outr[tid + 256] = o1;

    float4* at = (float4*)(g_At + (size_t)row * D);
    at[tid] = tf32r4(o0);
    at[tid + 256] = tf32r4(o1);
}

// ---------------- weight convert: tf32-rounded W -----------------------------
__global__ __launch_bounds__(256) void conv_w_kernel(const float* __restrict__ wq,
                                                     const float* __restrict__ wk,
                                                     const float* __restrict__ wv) {
    int j = blockIdx.x;                    // weight row (output feature)
    int wsel = blockIdx.y;                 // 0..2
    const float* W = (wsel == 0) ? wq : (wsel == 1) ? wk : wv;
    float4* dst = (float4*)(g_Wt + (size_t)wsel * ((size_t)D * D) + (size_t)j * D);
    const float4* src = (const float4*)(W + (size_t)j * D);
    int tid = threadIdx.x;
    dst[tid] = tf32r4(src[tid]);
    dst[tid + 256] = tf32r4(src[tid + 256]);
}

// ---------------- QKV GEMM via mma.sync tf32 m16n8k8 ------------------------
// C[4096, 2048] = At @ Wt^T, K=2048, grid (16, 32, 3), warp tile 64x32
__global__ __launch_bounds__(256, 2) void qkv_mma_kernel(const float* __restrict__ bq,
                                                         const float* __restrict__ bk,
                                                         const float* __restrict__ bv) {
    extern __shared__ __align__(128) char sm[];
    uint32_t sbase = smem_u32(sm);

    int tid = threadIdx.x;
    int lane = tid & 31;
    int wid = tid >> 5;
    int warp_m = wid >> 2;        // 0..1  -> 64-row slab
    int warp_n = wid & 3;         // 0..3  -> 32-col slab
    int bx = blockIdx.x;          // N tile
    int by = blockIdx.y;          // M tile
    int bz = blockIdx.z;          // q/k/v

    const float* bias = (bz == 0) ? bq : (bz == 1) ? bk : bv;
    float* C = (bz == 0) ? g_q : (bz == 1) ? g_k : g_v;
    const char* Abase = (const char*)g_At;                                 // row stride 8192 B
    const char* Bbase = (const char*)(g_Wt + (size_t)bz * ((size_t)D * D)); // row stride 8192 B

    auto load_stage = [&](int st, int j) {
        size_t koff = (size_t)j * 128;     // 32 fp32 = 128 B per iter
        uint32_t sA = sbase + st * GSTAGE_BYTES;
        uint32_t sB = sA + 16384;
        #pragma unroll
        for (int i = 0; i < 4; i++) {
            int idx = tid + i * 256;
            int row = idx >> 3;
            int c16 = idx & 7;
            uint32_t dst = sA + row * 128 + ((c16 ^ (row & 7)) << 4);
            cp16(dst, Abase + (size_t)(by * GBM + row) * 8192 + koff + c16 * 16);
        }
        #pragma unroll
        for (int i = 0; i < 4; i++) {
            int idx = tid + i * 256;
            int row = idx >> 3;
            int c16 = idx & 7;
            uint32_t dst = sB + row * 128 + ((c16 ^ (row & 7)) << 4);
            cp16(dst, Bbase + (size_t)(bx * GBN + row) * 8192 + koff + c16 * 16);
        }
    };

    float acc[4][4][4];
    #pragma unroll
    for (int mf = 0; mf < 4; mf++)
        #pragma unroll
        for (int nf = 0; nf < 4; nf++)
            #pragma unroll
            for (int q = 0; q < 4; q++) acc[mf][nf][q] = 0.f;

    load_stage(0, 0);
    cp_commit();
    load_stage(1, 1);
    cp_commit();

    int arow_off = warp_m * 64 + (lane & 15);   // A rows (per mf +16)
    int brow_off = warp_n * 32 + (lane & 15);   // B rows (per nf2 +16)
    int khalf = lane >> 4;                      // 16B half within the 32B k8 group
    int swz_x = lane & 7;

    for (int it = 0; it < KITERS; it++) {
        cp_wait<1>();
        __syncthreads();
        if (it + 2 < KITERS) load_stage((it + 2) % GSTAGES, it + 2);
        cp_commit();

        uint32_t sA = sbase + (it % GSTAGES) * GSTAGE_BYTES;
        uint32_t sB = sA + 16384;

        #pragma unroll
        for (int g = 0; g < 4; g++) {       // four k8 groups per 128B row
            uint32_t swz = (uint32_t)(((g * 2 + khalf) ^ swz_x) << 4);
            uint32_t a[4][4];
            uint32_t bf[4][2];
            #pragma unroll
            for (int mf = 0; mf < 4; mf++) {
                uint32_t addr = sA + (uint32_t)(arow_off + mf * 16) * 128 + swz;
                LDSM4(a[mf][0], a[mf][1], a[mf][2], a[mf][3], addr);
            }
            #pragma unroll
            for (int nf2 = 0; nf2 < 2; nf2++) {
                uint32_t r0, r1, r2, r3;
                uint32_t addr = sB + (uint32_t)(brow_off + nf2 * 16) * 128 + swz;
                LDSM4(r0, r1, r2, r3, addr);
                bf[nf2 * 2 + 0][0] = r0; bf[nf2 * 2 + 1][0] = r1;
                bf[nf2 * 2 + 0][1] = r2; bf[nf2 * 2 + 1][1] = r3;
            }
            #pragma unroll
            for (int mf = 0; mf < 4; mf++)
                #pragma unroll
                for (int nf = 0; nf < 4; nf++)
                    asm volatile(
                        "mma.sync.aligned.m16n8k8.row.col.f32.tf32.tf32.f32 "
                        "{%0,%1,%2,%3}, {%4,%5,%6,%7}, {%8,%9}, {%0,%1,%2,%3};"
                        : "+f"(acc[mf][nf][0]), "+f"(acc[mf][nf][1]),
                          "+f"(acc[mf][nf][2]), "+f"(acc[mf][nf][3])
                        : "r"(a[mf][0]), "r"(a[mf][1]), "r"(a[mf][2]), "r"(a[mf][3]),
                          "r"(bf[nf][0]), "r"(bf[nf][1]));
        }
        __syncthreads();
    }

    // epilogue: direct stores with bias
    int row_base = by * GBM + warp_m * 64 + (lane >> 2);
    int col_base = bx * GBN + warp_n * 32 + 2 * (lane & 3);
    #pragma unroll
    for (int nf = 0; nf < 4; nf++) {
        int c = col_base + nf * 8;
        float b0 = bias[c], b1 = bias[c + 1];
        #pragma unroll
        for (int mf = 0; mf < 4; mf++) {
            int r0 = row_base + mf * 16;
            float2 v0 = make_float2(acc[mf][nf][0] + b0, acc[mf][nf][1] + b1);
            float2 v1 = make_float2(acc[mf][nf][2] + b0, acc[mf][nf][3] + b1);
            *(float2*)(C + (size_t)r0 * D + c) = v0;
            *(float2*)(C + (size_t)(r0 + 8) * D + c) = v1;
        }
    }
}

// ---------------- scores partial: S_part[ks][b] = q.k over K chunk ----------
__global__ __launch_bounds__(256) void scores_kernel() {
    int ks = blockIdx.x;
    int b = blockIdx.y;
    const float* Qb = g_q + (size_t)b * NA * D + (size_t)ks * SCORE_KCHUNK;
    const float* Kb = g_k + (size_t)b * NA * D + (size_t)ks * SCORE_KCHUNK;
    __shared__ float Qs[32][68];
    __shared__ float Ks[32][68];
    int tid = threadIdx.x;
    int lr = tid >> 3;
    int lk = (tid & 7) << 2;
    int tm = tid >> 4, tn = tid & 15;
    float acc[4][4];
    #pragma unroll
    for (int i = 0; i < 4; i++)
        #pragma unroll
        for (int j = 0; j < 4; j++) acc[i][j] = 0.f;

    for (int k0 = 0; k0 < SCORE_KCHUNK; k0 += 32) {
        float4 q0 = *(const float4*)(Qb + (size_t)lr * D + k0 + lk);
        float4 q1 = *(const float4*)(Qb + (size_t)(lr + 32) * D + k0 + lk);
        float4 c0 = *(const float4*)(Kb + (size_t)lr * D + k0 + lk);
        float4 c1 = *(const float4*)(Kb + (size_t)(lr + 32) * D + k0 + lk);
        __syncthreads();
        Qs[lk + 0][lr] = q0.x; Qs[lk + 1][lr] = q0.y; Qs[lk + 2][lr] = q0.z; Qs[lk + 3][lr] = q0.w;
        Qs[lk + 0][lr + 32] = q1.x; Qs[lk + 1][lr + 32] = q1.y; Qs[lk + 2][lr + 32] = q1.z; Qs[lk + 3][lr + 32] = q1.w;
        Ks[lk + 0][lr] = c0.x; Ks[lk + 1][lr] = c0.y; Ks[lk + 2][lr] = c0.z; Ks[lk + 3][lr] = c0.w;
        Ks[lk + 0][lr + 32] = c1.x; Ks[lk + 1][lr + 32] = c1.y; Ks[lk + 2][lr + 32] = c1.z; Ks[lk + 3][lr + 32] = c1.w;
        __syncthreads();
        #pragma unroll
        for (int kk = 0; kk < 32; kk++) {
            float a[4], c[4];
            *(float4*)a = *(const float4*)(&Qs[kk][tm * 4]);
            *(float4*)c = *(const float4*)(&Ks[kk][tn * 4]);
            #pragma unroll
            for (int i = 0; i < 4; i++)
                #pragma unroll
                for (int j = 0; j < 4; j++)
                    acc[i][j] += a[i] * c[j];
        }
    }
    float* dst = g_spart + ((size_t)ks * BATCH + b) * 4096;
    #pragma unroll
    for (int i = 0; i < 4; i++)
        #pragma unroll
        for (int j = 0; j < 4; j++)
            dst[(tm * 4 + i) * 64 + (tn * 4 + j)] = acc[i][j];
}

// ---------------- Sinkhorn (sums partials, applies 1/sqrt(D)) ---------------
__global__ __launch_bounds__(1024) void sinkhorn_kernel(float* __restrict__ attn_out) {
    int b = blockIdx.x;
    __shared__ float m[64][65];
    int tid = threadIdx.x;
    const float invS = 1.0f / 45.254833995939045f;
    const float* p0 = g_spart + (size_t)b * 4096;
    const size_t pstride = (size_t)BATCH * 4096;
    for (int i = tid; i < 4096; i += 1024) {
        float v = p0[i] + p0[i + pstride] + p0[i + 2 * pstride] + p0[i + 3 * pstride];
        m[i >> 6][i & 63] = v * invS;
    }
    __syncthreads();
    int w = tid >> 5, lane = tid & 31;
    for (int it = 0; it < SINKHORN_ITERS; it++) {
        #pragma unroll
        for (int rr = 0; rr < 2; rr++) {
            int r = w * 2 + rr;
            float x0 = m[r][lane], x1 = m[r][lane + 32];
            float mx = fmaxf(x0, x1);
            #pragma unroll
            for (int o = 16; o; o >>= 1) mx = fmaxf(mx, __shfl_xor_sync(0xFFFFFFFFu, mx, o));
            float s = expf(x0 - mx) + expf(x1 - mx);
            #pragma unroll
            for (int o = 16; o; o >>= 1) s += __shfl_xor_sync(0xFFFFFFFFu, s, o);
            float lse = mx + logf(s);
            m[r][lane] = x0 - lse;
            m[r][lane + 32] = x1 - lse;
        }
        __syncthreads();
        #pragma unroll
        for (int cc = 0; cc < 2; cc++) {
            int c = w * 2 + cc;
            float x0 = m[lane][c], x1 = m[lane + 32][c];
            float mx = fmaxf(x0, x1);
            #pragma unroll
            for (int o = 16; o; o >>= 1) mx = fmaxf(mx, __shfl_xor_sync(0xFFFFFFFFu, mx, o));
            float s = expf(x0 - mx) + expf(x1 - mx);
            #pragma unroll
            for (int o = 16; o; o >>= 1) s += __shfl_xor_sync(0xFFFFFFFFu, s, o);
            float lse = mx + logf(s);
            m[lane][c] = x0 - lse;
            m[lane + 32][c] = x1 - lse;
        }
        __syncthreads();
    }
    for (int i = tid; i < 4096; i += 1024) {
        float e = expf(m[i >> 6][i & 63]);
        g_attn[(size_t)b * 4096 + i] = e;
        if (attn_out) attn_out[(size_t)b * 4096 + i] = e;
    }
}

// ---------------- attended = attn @ V, fused mix ----------------------------
__global__ __launch_bounds__(256) void attended_kernel() {
    int d0 = blockIdx.x * 128;
    int b = blockIdx.y;
    __shared__ float attn_s[64][64];
    __shared__ float4 Vs[64][32];
    int tid = threadIdx.x;
    const float* ab = g_attn + (size_t)b * 4096;
    for (int i = tid; i < 4096; i += 256) attn_s[i >> 6][i & 63] = ab[i];
    const float* Vb = g_v + (size_t)b * NA * D;
    {
        int r = tid >> 5;
        int c = tid & 31;
        #pragma unroll
        for (int p = 0; p < 8; p++)
            Vs[r + p * 8][c] = *(const float4*)(Vb + (size_t)(r + p * 8) * D + d0 + c * 4);
    }
    __syncthreads();
    int tx = tid & 31, ty = tid >> 5;
    float4 acc[8];
    #pragma unroll
    for (int i = 0; i < 8; i++) acc[i] = make_float4(0.f, 0.f, 0.f, 0.f);
    for (int mm = 0; mm < 64; mm++) {
        float4 v4 = Vs[mm][tx];
        #pragma unroll
        for (int i = 0; i < 8; i++) {
            float a = attn_s[ty * 8 + i][mm];
            acc[i].x += a * v4.x;
            acc[i].y += a * v4.y;
            acc[i].z += a * v4.z;
            acc[i].w += a * v4.w;
        }
    }
    #pragma unroll
    for (int i = 0; i < 8; i++) {
        int n = ty * 8 + i;
        size_t off = ((size_t)(b * 64 + n)) * D + d0 + tx * 4;
        float4 nm = *(const float4*)(g_normed + off);
        float4 o;
        o.x = ID_PRESERVE * nm.x + (1.0f - ID_PRESERVE) * acc[i].x;
        o.y = ID_PRESERVE * nm.y + (1.0f - ID_PRESERVE) * acc[i].y;
        o.z = ID_PRESERVE * nm.z + (1.0f - ID_PRESERVE) * acc[i].z;
        o.w = ID_PRESERVE * nm.w + (1.0f - ID_PRESERVE) * acc[i].w;
        *(float4*)(g_mixed + off) = o;
    }
}

// ---------------- epilogue ---------------------------------------------------
__global__ __launch_bounds__(256) void epilogue_kernel(const float* __restrict__ x,
                                                       const float* __restrict__ biases,
                                                       const float* __restrict__ scales,
                                                       float* __restrict__ out) {
    __shared__ float red[8];
    int row = blockIdx.x;
    int n = row & 63;
    int tid = threadIdx.x;
    float sc = scales[n];
    const float4* mr = (const float4*)(g_mixed + (size_t)row * D);
    const float4* br = (const float4*)(biases + (size_t)n * D);
    float4 m0 = mr[tid], m1 = mr[tid + 256];
    float4 b0 = br[tid], b1 = br[tid + 256];
    float4 s0, s1;
    s0.x = (m0.x + b0.x) * sc; s0.y = (m0.y + b0.y) * sc;
    s0.z = (m0.z + b0.z) * sc; s0.w = (m0.w + b0.w) * sc;
    s1.x = (m1.x + b1.x) * sc; s1.y = (m1.y + b1.y) * sc;
    s1.z = (m1.z + b1.z) * sc; s1.w = (m1.w + b1.w) * sc;
    float ss = s0.x*s0.x + s0.y*s0.y + s0.z*s0.z + s0.w*s0.w
             + s1.x*s1.x + s1.y*s1.y + s1.z*s1.z + s1.w*s1.w;
    #pragma unroll
    for (int o = 16; o; o >>= 1) ss += __shfl_xor_sync(0xFFFFFFFFu, ss, o);
    if ((tid & 31) == 0) red[tid >> 5] = ss;
    __syncthreads();
    float tot = 0.f;
    #pragma unroll
    for (int i = 0; i < 8; i++) tot += red[i];
    float norm = sqrtf(tot);
    float inv = 1.0f / fmaxf(1.0f, norm / SIGNAL_BOUND);
    const float4* xr = (const float4*)(x + (size_t)row * D);
    float4 x0 = xr[tid], x1 = xr[tid + 256];
    float4 o0, o1;
    o0.x = x0.x + s0.x * inv; o0.y = x0.y + s0.y * inv;
    o0.z = x0.z + s0.z * inv; o0.w = x0.w + s0.w * inv;
    o1.x = x1.x + s1.x * inv; o1.y = x1.y + s1.y * inv;
    o1.z = x1.z + s1.z * inv; o1.w = x1.w + s1.w * inv;
    float4* outr = (float4*)(out + (size_t)row * D);
    outr[tid] = o0;
    outr[tid + 256] = o1;
}

// ---------------- launch -----------------------------------------------------
extern "C" void kernel_launch(void* const* d_in, const int* in_sizes, int n_in,
                              void* d_out, int out_size) {
    const float* agent_states  = (const float*)d_in[0];
    const float* ln_w          = (const float*)d_in[1];
    const float* ln_b          = (const float*)d_in[2];
    const float* wq            = (const float*)d_in[3];
    const float* bq            = (const float*)d_in[4];
    const float* wk            = (const float*)d_in[5];
    const float* bk            = (const float*)d_in[6];
    const float* wv            = (const float*)d_in[7];
    const float* bv            = (const float*)d_in[8];
    const float* agent_biases  = (const float*)d_in[9];
    const float* scale_factors = (const float*)d_in[10];
    float* out = (float*)d_out;
    float* attn_out = (out_size >= ROWS * D + BATCH * NA * NA) ? (out + (size_t)ROWS * D)
                                                               : nullptr;

    const int DYN_SMEM = GSTAGES * GSTAGE_BYTES;   // 96 KB
    cudaFuncSetAttribute(qkv_mma_kernel, cudaFuncAttributeMaxDynamicSharedMemorySize, DYN_SMEM);

    ln_kernel<<<ROWS, 256>>>(agent_states, ln_w, ln_b);
    conv_w_kernel<<<dim3(D, 3), 256>>>(wq, wk, wv);
    qkv_mma_kernel<<<dim3(D / GBN, ROWS / GBM, 3), 256, DYN_SMEM>>>(bq, bk, bv);
    scores_kernel<<<dim3(SCORE_KSPLIT, BATCH), 256>>>();
    sinkhorn_kernel<<<BATCH, 1024>>>(attn_out);
    attended_kernel<<<dim3(16, BATCH), 256>>>();
    epilogue_kernel<<<ROWS, 256>>>(agent_states, agent_biases, scale_factors, out);
}

// round 12
// speedup vs baseline: 2.2518x; 1.5514x over previous
#include <cuda_runtime.h>
#include <math.h>
#include <stdint.h>

#define D 2048
#define NA 64
#define BATCH 64
#define ROWS (BATCH * NA)        // 4096
#define LN_EPS 1e-5f
#define ID_PRESERVE 0.1f
#define SIGNAL_BOUND 1.0f
#define SINKHORN_ITERS 50

// GEMM: CTA 128x128, fp16 single pass K=2048, BK=64 fp16 (128B rows), 3-stage
#define GBM 128
#define GBN 128
#define KITERS 32                // 2048 / 64
#define GSTAGES 3
#define GSTAGE_BYTES 32768       // A 16KB + B 16KB (128 rows x 128B each)

#define SCORE_KSPLIT 4
#define SCORE_KCHUNK (D / SCORE_KSPLIT)   // 512

// ---------------- scratch (device globals; no allocation allowed) ----------
__device__ float g_normed[ROWS * D];
__device__ float g_q[ROWS * D];
__device__ float g_k[ROWS * D];
__device__ float g_v[ROWS * D];
__device__ float g_mixed[ROWS * D];
__device__ float g_spart[SCORE_KSPLIT * BATCH * NA * NA];
__device__ float g_attn[BATCH * NA * NA];
// fp16 operands stored as packed u32 pairs (no cuda_fp16.h dependence)
__device__ uint32_t g_Ah[(size_t)ROWS * D / 2];          // [4096, 2048] fp16
__device__ uint32_t g_Wh[3ull * D * D / 2];              // 3 x [2048, 2048] fp16

// ---------------- PTX helpers ------------------------------------------------
__device__ __forceinline__ uint32_t smem_u32(const void* p) {
    uint32_t a;
    asm("{ .reg .u64 t; cvta.to.shared.u64 t, %1; cvt.u32.u64 %0, t; }" : "=r"(a) : "l"(p));
    return a;
}
__device__ __forceinline__ void cp16(uint32_t dst, const void* src) {
    asm volatile("cp.async.cg.shared.global [%0], [%1], 16;" :: "r"(dst), "l"(src));
}
__device__ __forceinline__ void cp_commit() { asm volatile("cp.async.commit_group;" ::: "memory"); }
template <int N>
__device__ __forceinline__ void cp_wait() { asm volatile("cp.async.wait_group %0;" :: "n"(N) : "memory"); }

#define LDSM4(r0, r1, r2, r3, addr) \
    asm volatile("ldmatrix.sync.aligned.m8n8.x4.shared.b16 {%0,%1,%2,%3}, [%4];" \
                 : "=r"(r0), "=r"(r1), "=r"(r2), "=r"(r3) : "r"(addr))

// pack two fp32 -> fp16x2 in a b32 register (pure PTX, no half headers)
__device__ __forceinline__ uint32_t f16x2(float lo, float hi) {
    uint32_t r;
    asm("{ .reg .f16 a, b;\n\t"
        "cvt.rn.f16.f32 a, %1;\n\t"
        "cvt.rn.f16.f32 b, %2;\n\t"
        "mov.b32 %0, {a, b}; }"
        : "=r"(r) : "f"(lo), "f"(hi));
    return r;
}
__device__ __forceinline__ uint2 h4(float4 v) {
    uint2 u;
    u.x = f16x2(v.x, v.y);
    u.y = f16x2(v.z, v.w);
    return u;
}

// ---------------- LayerNorm + emit fp16 A ------------------------------------
__global__ __launch_bounds__(256) void ln_kernel(const float* __restrict__ x,
                                                 const float* __restrict__ w,
                                                 const float* __restrict__ b) {
    __shared__ float redS[8], redQ[8];
    int row = blockIdx.x;
    int tid = threadIdx.x;
    const float4* xr = (const float4*)(x + (size_t)row * D);
    float4 v0 = xr[tid];
    float4 v1 = xr[tid + 256];
    float s  = v0.x + v0.y + v0.z + v0.w + v1.x + v1.y + v1.z + v1.w;
    float ss = v0.x*v0.x + v0.y*v0.y + v0.z*v0.z + v0.w*v0.w
             + v1.x*v1.x + v1.y*v1.y + v1.z*v1.z + v1.w*v1.w;
    #pragma unroll
    for (int o = 16; o; o >>= 1) {
        s  += __shfl_xor_sync(0xFFFFFFFFu, s, o);
        ss += __shfl_xor_sync(0xFFFFFFFFu, ss, o);
    }
    int wid = tid >> 5;
    if ((tid & 31) == 0) { redS[wid] = s; redQ[wid] = ss; }
    __syncthreads();
    float ts = 0.f, tq = 0.f;
    #pragma unroll
    for (int i = 0; i < 8; i++) { ts += redS[i]; tq += redQ[i]; }
    float mean = ts * (1.0f / D);
    float var  = tq * (1.0f / D) - mean * mean;
    float r = 1.0f / sqrtf(var + LN_EPS);

    const float4* wr = (const float4*)w;
    const float4* br = (const float4*)b;
    float4 w0 = wr[tid], w1 = wr[tid + 256];
    float4 b0 = br[tid], b1 = br[tid + 256];
    float4 o0, o1;
    o0.x = (v0.x - mean) * r * w0.x + b0.x;
    o0.y = (v0.y - mean) * r * w0.y + b0.y;
    o0.z = (v0.z - mean) * r * w0.z + b0.z;
    o0.w = (v0.w - mean) * r * w0.w + b0.w;
    o1.x = (v1.x - mean) * r * w1.x + b1.x;
    o1.y = (v1.y - mean) * r * w1.y + b1.y;
    o1.z = (v1.z - mean) * r * w1.z + b1.z;
    o1.w = (v1.w - mean) * r * w1.w + b1.w;
    float4* outr = (float4*)(g_normed + (size_t)row * D);
    outr[tid] = o0;
    outr[tid + 256] = o1;

    uint2* arow = (uint2*)(g_Ah + (size_t)row * (D / 2));
    arow[tid] = h4(o0);
    arow[tid + 256] = h4(o1);
}

// ---------------- weight convert: fp16 W -------------------------------------
__global__ __launch_bounds__(256) void conv_w_kernel(const float* __restrict__ wq,
                                                     const float* __restrict__ wk,
                                                     const float* __restrict__ wv) {
    int j = blockIdx.x;                    // weight row (output feature)
    int wsel = blockIdx.y;                 // 0..2
    const float* W = (wsel == 0) ? wq : (wsel == 1) ? wk : wv;
    uint2* dst = (uint2*)(g_Wh + (size_t)wsel * ((size_t)D * D / 2) + (size_t)j * (D / 2));
    const float4* src = (const float4*)(W + (size_t)j * D);
    int tid = threadIdx.x;
    dst[tid] = h4(src[tid]);
    dst[tid + 256] = h4(src[tid + 256]);
}

// ---------------- QKV GEMM via mma.sync fp16 m16n8k16 ------------------------
// C[4096, 2048] = Ah @ Wh^T, K=2048, grid (16, 32, 3), warp tile 64x32
__global__ __launch_bounds__(256, 2) void qkv_mma_kernel(const float* __restrict__ bq,
                                                         const float* __restrict__ bk,
                                                         const float* __restrict__ bv) {
    extern __shared__ __align__(128) char sm[];
    uint32_t sbase = smem_u32(sm);

    int tid = threadIdx.x;
    int lane = tid & 31;
    int wid = tid >> 5;
    int warp_m = wid >> 2;        // 0..1  -> 64-row slab
    int warp_n = wid & 3;         // 0..3  -> 32-col slab
    int bx = blockIdx.x;          // N tile
    int by = blockIdx.y;          // M tile
    int bz = blockIdx.z;          // q/k/v

    const float* bias = (bz == 0) ? bq : (bz == 1) ? bk : bv;
    float* C = (bz == 0) ? g_q : (bz == 1) ? g_k : g_v;
    const char* Abase = (const char*)g_Ah;                                     // row stride 4096 B
    const char* Bbase = (const char*)(g_Wh + (size_t)bz * ((size_t)D * D / 2)); // row stride 4096 B

    auto load_stage = [&](int st, int j) {
        size_t koff = (size_t)j * 128;     // 64 fp16 = 128 B per iter
        uint32_t sA = sbase + st * GSTAGE_BYTES;
        uint32_t sB = sA + 16384;
        #pragma unroll
        for (int i = 0; i < 4; i++) {
            int idx = tid + i * 256;
            int row = idx >> 3;
            int c16 = idx & 7;
            uint32_t dst = sA + row * 128 + ((c16 ^ (row & 7)) << 4);
            cp16(dst, Abase + (size_t)(by * GBM + row) * 4096 + koff + c16 * 16);
        }
        #pragma unroll
        for (int i = 0; i < 4; i++) {
            int idx = tid + i * 256;
            int row = idx >> 3;
            int c16 = idx & 7;
            uint32_t dst = sB + row * 128 + ((c16 ^ (row & 7)) << 4);
            cp16(dst, Bbase + (size_t)(bx * GBN + row) * 4096 + koff + c16 * 16);
        }
    };

    float acc[4][4][4];
    #pragma unroll
    for (int mf = 0; mf < 4; mf++)
        #pragma unroll
        for (int nf = 0; nf < 4; nf++)
            #pragma unroll
            for (int q = 0; q < 4; q++) acc[mf][nf][q] = 0.f;

    load_stage(0, 0);
    cp_commit();
    load_stage(1, 1);
    cp_commit();

    int arow_off = warp_m * 64 + (lane & 15);   // A rows (per mf +16)
    int brow_off = warp_n * 32 + (lane & 15);   // B rows (per nf2 +16)
    int khalf = lane >> 4;                      // 16B half within the 32B k16 group
    int swz_x = lane & 7;

    for (int it = 0; it < KITERS; it++) {
        cp_wait<1>();
        __syncthreads();
        if (it + 2 < KITERS) load_stage((it + 2) % GSTAGES, it + 2);
        cp_commit();

        uint32_t sA = sbase + (it % GSTAGES) * GSTAGE_BYTES;
        uint32_t sB = sA + 16384;

        #pragma unroll
        for (int ks = 0; ks < 4; ks++) {
            uint32_t swz = (uint32_t)(((ks * 2 + khalf) ^ swz_x) << 4);
            uint32_t a[4][4];
            uint32_t bf[4][2];
            #pragma unroll
            for (int mf = 0; mf < 4; mf++) {
                uint32_t addr = sA + (uint32_t)(arow_off + mf * 16) * 128 + swz;
                LDSM4(a[mf][0], a[mf][1], a[mf][2], a[mf][3], addr);
            }
            #pragma unroll
            for (int nf2 = 0; nf2 < 2; nf2++) {
                uint32_t r0, r1, r2, r3;
                uint32_t addr = sB + (uint32_t)(brow_off + nf2 * 16) * 128 + swz;
                LDSM4(r0, r1, r2, r3, addr);
                bf[nf2 * 2 + 0][0] = r0; bf[nf2 * 2 + 1][0] = r1;
                bf[nf2 * 2 + 0][1] = r2; bf[nf2 * 2 + 1][1] = r3;
            }
            #pragma unroll
            for (int mf = 0; mf < 4; mf++)
                #pragma unroll
                for (int nf = 0; nf < 4; nf++)
                    asm volatile(
                        "mma.sync.aligned.m16n8k16.row.col.f32.f16.f16.f32 "
                        "{%0,%1,%2,%3}, {%4,%5,%6,%7}, {%8,%9}, {%0,%1,%2,%3};"
                        : "+f"(acc[mf][nf][0]), "+f"(acc[mf][nf][1]),
                          "+f"(acc[mf][nf][2]), "+f"(acc[mf][nf][3])
                        : "r"(a[mf][0]), "r"(a[mf][1]), "r"(a[mf][2]), "r"(a[mf][3]),
                          "r"(bf[nf][0]), "r"(bf[nf][1]));
        }
        __syncthreads();
    }

    // epilogue: direct stores with bias
    int row_base = by * GBM + warp_m * 64 + (lane >> 2);
    int col_base = bx * GBN + warp_n * 32 + 2 * (lane & 3);
    #pragma unroll
    for (int nf = 0; nf < 4; nf++) {
        int c = col_base + nf * 8;
        float b0 = bias[c], b1 = bias[c + 1];
        #pragma unroll
        for (int mf = 0; mf < 4; mf++) {
            int r0 = row_base + mf * 16;
            float2 v0 = make_float2(acc[mf][nf][0] + b0, acc[mf][nf][1] + b1);
            float2 v1 = make_float2(acc[mf][nf][2] + b0, acc[mf][nf][3] + b1);
            *(float2*)(C + (size_t)r0 * D + c) = v0;
            *(float2*)(C + (size_t)(r0 + 8) * D + c) = v1;
        }
    }
}

// ---------------- scores partial: S_part[ks][b] = q.k over K chunk ----------
__global__ __launch_bounds__(256) void scores_kernel() {
    int ks = blockIdx.x;
    int b = blockIdx.y;
    const float* Qb = g_q + (size_t)b * NA * D + (size_t)ks * SCORE_KCHUNK;
    const float* Kb = g_k + (size_t)b * NA * D + (size_t)ks * SCORE_KCHUNK;
    __shared__ float Qs[32][68];
    __shared__ float Ks[32][68];
    int tid = threadIdx.x;
    int lr = tid >> 3;
    int lk = (tid & 7) << 2;
    int tm = tid >> 4, tn = tid & 15;
    float acc[4][4];
    #pragma unroll
    for (int i = 0; i < 4; i++)
        #pragma unroll
        for (int j = 0; j < 4; j++) acc[i][j] = 0.f;

    for (int k0 = 0; k0 < SCORE_KCHUNK; k0 += 32) {
        float4 q0 = *(const float4*)(Qb + (size_t)lr * D + k0 + lk);
        float4 q1 = *(const float4*)(Qb + (size_t)(lr + 32) * D + k0 + lk);
        float4 c0 = *(const float4*)(Kb + (size_t)lr * D + k0 + lk);
        float4 c1 = *(const float4*)(Kb + (size_t)(lr + 32) * D + k0 + lk);
        __syncthreads();
        Qs[lk + 0][lr] = q0.x; Qs[lk + 1][lr] = q0.y; Qs[lk + 2][lr] = q0.z; Qs[lk + 3][lr] = q0.w;
        Qs[lk + 0][lr + 32] = q1.x; Qs[lk + 1][lr + 32] = q1.y; Qs[lk + 2][lr + 32] = q1.z; Qs[lk + 3][lr + 32] = q1.w;
        Ks[lk + 0][lr] = c0.x; Ks[lk + 1][lr] = c0.y; Ks[lk + 2][lr] = c0.z; Ks[lk + 3][lr] = c0.w;
        Ks[lk + 0][lr + 32] = c1.x; Ks[lk + 1][lr + 32] = c1.y; Ks[lk + 2][lr + 32] = c1.z; Ks[lk + 3][lr + 32] = c1.w;
        __syncthreads();
        #pragma unroll
        for (int kk = 0; kk < 32; kk++) {
            float a[4], c[4];
            *(float4*)a = *(const float4*)(&Qs[kk][tm * 4]);
            *(float4*)c = *(const float4*)(&Ks[kk][tn * 4]);
            #pragma unroll
            for (int i = 0; i < 4; i++)
                #pragma unroll
                for (int j = 0; j < 4; j++)
                    acc[i][j] += a[i] * c[j];
        }
    }
    float* dst = g_spart + ((size_t)ks * BATCH + b) * 4096;
    #pragma unroll
    for (int i = 0; i < 4; i++)
        #pragma unroll
        for (int j = 0; j < 4; j++)
            dst[(tm * 4 + i) * 64 + (tn * 4 + j)] = acc[i][j];
}

// ---------------- Sinkhorn (sums partials, applies 1/sqrt(D)) ---------------
__global__ __launch_bounds__(1024) void sinkhorn_kernel(float* __restrict__ attn_out) {
    int b = blockIdx.x;
    __shared__ float m[64][65];
    int tid = threadIdx.x;
    const float invS = 1.0f / 45.254833995939045f;
    const float* p0 = g_spart + (size_t)b * 4096;
    const size_t pstride = (size_t)BATCH * 4096;
    for (int i = tid; i < 4096; i += 1024) {
        float v = p0[i] + p0[i + pstride] + p0[i + 2 * pstride] + p0[i + 3 * pstride];
        m[i >> 6][i & 63] = v * invS;
    }
    __syncthreads();
    int w = tid >> 5, lane = tid & 31;
    for (int it = 0; it < SINKHORN_ITERS; it++) {
        #pragma unroll
        for (int rr = 0; rr < 2; rr++) {
            int r = w * 2 + rr;
            float x0 = m[r][lane], x1 = m[r][lane + 32];
            float mx = fmaxf(x0, x1);
            #pragma unroll
            for (int o = 16; o; o >>= 1) mx = fmaxf(mx, __shfl_xor_sync(0xFFFFFFFFu, mx, o));
            float s = expf(x0 - mx) + expf(x1 - mx);
            #pragma unroll
            for (int o = 16; o; o >>= 1) s += __shfl_xor_sync(0xFFFFFFFFu, s, o);
            float lse = mx + logf(s);
            m[r][lane] = x0 - lse;
            m[r][lane + 32] = x1 - lse;
        }
        __syncthreads();
        #pragma unroll
        for (int cc = 0; cc < 2; cc++) {
            int c = w * 2 + cc;
            float x0 = m[lane][c], x1 = m[lane + 32][c];
            float mx = fmaxf(x0, x1);
            #pragma unroll
            for (int o = 16; o; o >>= 1) mx = fmaxf(mx, __shfl_xor_sync(0xFFFFFFFFu, mx, o));
            float s = expf(x0 - mx) + expf(x1 - mx);
            #pragma unroll
            for (int o = 16; o; o >>= 1) s += __shfl_xor_sync(0xFFFFFFFFu, s, o);
            float lse = mx + logf(s);
            m[lane][c] = x0 - lse;
            m[lane + 32][c] = x1 - lse;
        }
        __syncthreads();
    }
    for (int i = tid; i < 4096; i += 1024) {
        float e = expf(m[i >> 6][i & 63]);
        g_attn[(size_t)b * 4096 + i] = e;
        if (attn_out) attn_out[(size_t)b * 4096 + i] = e;
    }
}

// ---------------- attended = attn @ V, fused mix ----------------------------
__global__ __launch_bounds__(256) void attended_kernel() {
    int d0 = blockIdx.x * 128;
    int b = blockIdx.y;
    __shared__ float attn_s[64][64];
    __shared__ float4 Vs[64][32];
    int tid = threadIdx.x;
    const float* ab = g_attn + (size_t)b * 4096;
    for (int i = tid; i < 4096; i += 256) attn_s[i >> 6][i & 63] = ab[i];
    const float* Vb = g_v + (size_t)b * NA * D;
    {
        int r = tid >> 5;
        int c = tid & 31;
        #pragma unroll
        for (int p = 0; p < 8; p++)
            Vs[r + p * 8][c] = *(const float4*)(Vb + (size_t)(r + p * 8) * D + d0 + c * 4);
    }
    __syncthreads();
    int tx = tid & 31, ty = tid >> 5;
    float4 acc[8];
    #pragma unroll
    for (int i = 0; i < 8; i++) acc[i] = make_float4(0.f, 0.f, 0.f, 0.f);
    for (int mm = 0; mm < 64; mm++) {
        float4 v4 = Vs[mm][tx];
        #pragma unroll
        for (int i = 0; i < 8; i++) {
            float a = attn_s[ty * 8 + i][mm];
            acc[i].x += a * v4.x;
            acc[i].y += a * v4.y;
            acc[i].z += a * v4.z;
            acc[i].w += a * v4.w;
        }
    }
    #pragma unroll
    for (int i = 0; i < 8; i++) {
        int n = ty * 8 + i;
        size_t off = ((size_t)(b * 64 + n)) * D + d0 + tx * 4;
        float4 nm = *(const float4*)(g_normed + off);
        float4 o;
        o.x = ID_PRESERVE * nm.x + (1.0f - ID_PRESERVE) * acc[i].x;
        o.y = ID_PRESERVE * nm.y + (1.0f - ID_PRESERVE) * acc[i].y;
        o.z = ID_PRESERVE * nm.z + (1.0f - ID_PRESERVE) * acc[i].z;
        o.w = ID_PRESERVE * nm.w + (1.0f - ID_PRESERVE) * acc[i].w;
        *(float4*)(g_mixed + off) = o;
    }
}

// ---------------- epilogue ---------------------------------------------------
__global__ __launch_bounds__(256) void epilogue_kernel(const float* __restrict__ x,
                                                       const float* __restrict__ biases,
                                                       const float* __restrict__ scales,
                                                       float* __restrict__ out) {
    __shared__ float red[8];
    int row = blockIdx.x;
    int n = row & 63;
    int tid = threadIdx.x;
    float sc = scales[n];
    const float4* mr = (const float4*)(g_mixed + (size_t)row * D);
    const float4* br = (const float4*)(biases + (size_t)n * D);
    float4 m0 = mr[tid], m1 = mr[tid + 256];
    float4 b0 = br[tid], b1 = br[tid + 256];
    float4 s0, s1;
    s0.x = (m0.x + b0.x) * sc; s0.y = (m0.y + b0.y) * sc;
    s0.z = (m0.z + b0.z) * sc; s0.w = (m0.w + b0.w) * sc;
    s1.x = (m1.x + b1.x) * sc; s1.y = (m1.y + b1.y) * sc;
    s1.z = (m1.z + b1.z) * sc; s1.w = (m1.w + b1.w) * sc;
    float ss = s0.x*s0.x + s0.y*s0.y + s0.z*s0.z + s0.w*s0.w
             + s1.x*s1.x + s1.y*s1.y + s1.z*s1.z + s1.w*s1.w;
    #pragma unroll
    for (int o = 16; o; o >>= 1) ss += __shfl_xor_sync(0xFFFFFFFFu, ss, o);
    if ((tid & 31) == 0) red[tid >> 5] = ss;
    __syncthreads();
    float tot = 0.f;
    #pragma unroll
    for (int i = 0; i < 8; i++) tot += red[i];
    float norm = sqrtf(tot);
    float inv = 1.0f / fmaxf(1.0f, norm / SIGNAL_BOUND);
    const float4* xr = (const float4*)(x + (size_t)row * D);
    float4 x0 = xr[tid], x1 = xr[tid + 256];
    float4 o0, o1;
    o0.x = x0.x + s0.x * inv; o0.y = x0.y + s0.y * inv;
    o0.z = x0.z + s0.z * inv; o0.w = x0.w + s0.w * inv;
    o1.x = x1.x + s1.x * inv; o1.y = x1.y + s1.y * inv;
    o1.z = x1.z + s1.z * inv; o1.w = x1.w + s1.w * inv;
    float4* outr = (float4*)(out + (size_t)row * D);
    outr[tid] = o0;
    outr[tid + 256] = o1;
}

// ---------------- launch -----------------------------------------------------
extern "C" void kernel_launch(void* const* d_in, const int* in_sizes, int n_in,
                              void* d_out, int out_size) {
    const float* agent_states  = (const float*)d_in[0];
    const float* ln_w          = (const float*)d_in[1];
    const float* ln_b          = (const float*)d_in[2];
    const float* wq            = (const float*)d_in[3];
    const float* bq            = (const float*)d_in[4];
    const float* wk            = (const float*)d_in[5];
    const float* bk            = (const float*)d_in[6];
    const float* wv            = (const float*)d_in[7];
    const float* bv            = (const float*)d_in[8];
    const float* agent_biases  = (const float*)d_in[9];
    const float* scale_factors = (const float*)d_in[10];
    float* out = (float*)d_out;
    float* attn_out = (out_size >= ROWS * D + BATCH * NA * NA) ? (out + (size_t)ROWS * D)
                                                               : nullptr;

    const int DYN_SMEM = GSTAGES * GSTAGE_BYTES;   // 96 KB
    cudaFuncSetAttribute(qkv_mma_kernel, cudaFuncAttributeMaxDynamicSharedMemorySize, DYN_SMEM);

    ln_kernel<<<ROWS, 256>>>(agent_states, ln_w, ln_b);
    conv_w_kernel<<<dim3(D, 3), 256>>>(wq, wk, wv);
    qkv_mma_kernel<<<dim3(D / GBN, ROWS / GBM, 3), 256, DYN_SMEM>>>(bq, bk, bv);
    scores_kernel<<<dim3(SCORE_KSPLIT, BATCH), 256>>>();
    sinkhorn_kernel<<<BATCH, 1024>>>(attn_out);
    attended_kernel<<<dim3(16, BATCH), 256>>>();
    epilogue_kernel<<<ROWS, 256>>>(agent_states, agent_biases, scale_factors, out);
}

// round 13
// speedup vs baseline: 2.4125x; 1.0714x over previous
#include <cuda_runtime.h>
#include <math.h>
#include <stdint.h>

#define D 2048
#define NA 64
#define BATCH 64
#define ROWS (BATCH * NA)        // 4096
#define LN_EPS 1e-5f
#define ID_PRESERVE 0.1f
#define SIGNAL_BOUND 1.0f
#define SINKHORN_ITERS 50

// GEMM: CTA 128x128, fp16 single pass K=2048, BK=64 fp16 (128B rows), 3-stage
#define GBM 128
#define GBN 128
#define KITERS 32                // 2048 / 64
#define GSTAGES 3
#define GSTAGE_BYTES 32768       // A 16KB + B 16KB (128 rows x 128B each)

#define SCORE_KSPLIT 4
#define SCORE_KCHUNK (D / SCORE_KSPLIT)   // 512 elems

// ---------------- scratch (device globals; no allocation allowed) ----------
__device__ float g_normed[ROWS * D];
__device__ float g_v[ROWS * D];
__device__ float g_mixed[ROWS * D];
__device__ float g_spart[SCORE_KSPLIT * BATCH * NA * NA];
__device__ float g_attn[BATCH * NA * NA];
// fp16 operands stored as packed u32 pairs (no cuda_fp16.h — triggers infra failure)
__device__ uint32_t g_Ah[(size_t)ROWS * D / 2];          // [4096, 2048] fp16
__device__ uint32_t g_Wh[3ull * D * D / 2];              // 3 x [2048, 2048] fp16
__device__ uint32_t g_qh[(size_t)ROWS * D / 2];          // q in fp16
__device__ uint32_t g_kh[(size_t)ROWS * D / 2];          // k in fp16

// ---------------- PTX helpers ------------------------------------------------
__device__ __forceinline__ uint32_t smem_u32(const void* p) {
    uint32_t a;
    asm("{ .reg .u64 t; cvta.to.shared.u64 t, %1; cvt.u32.u64 %0, t; }" : "=r"(a) : "l"(p));
    return a;
}
__device__ __forceinline__ void cp16(uint32_t dst, const void* src) {
    asm volatile("cp.async.cg.shared.global [%0], [%1], 16;" :: "r"(dst), "l"(src));
}
__device__ __forceinline__ void cp_commit() { asm volatile("cp.async.commit_group;" ::: "memory"); }
template <int N>
__device__ __forceinline__ void cp_wait() { asm volatile("cp.async.wait_group %0;" :: "n"(N) : "memory"); }

#define LDSM4(r0, r1, r2, r3, addr) \
    asm volatile("ldmatrix.sync.aligned.m8n8.x4.shared.b16 {%0,%1,%2,%3}, [%4];" \
                 : "=r"(r0), "=r"(r1), "=r"(r2), "=r"(r3) : "r"(addr))

#define MMA16816(acc, a, b0r, b1r) \
    asm volatile( \
        "mma.sync.aligned.m16n8k16.row.col.f32.f16.f16.f32 " \
        "{%0,%1,%2,%3}, {%4,%5,%6,%7}, {%8,%9}, {%0,%1,%2,%3};" \
        : "+f"((acc)[0]), "+f"((acc)[1]), "+f"((acc)[2]), "+f"((acc)[3]) \
        : "r"((a)[0]), "r"((a)[1]), "r"((a)[2]), "r"((a)[3]), \
          "r"(b0r), "r"(b1r))

// pack two fp32 -> fp16x2 in a b32 register (pure PTX, no half headers)
__device__ __forceinline__ uint32_t f16x2(float lo, float hi) {
    uint32_t r;
    asm("{ .reg .f16 a, b;\n\t"
        "cvt.rn.f16.f32 a, %1;\n\t"
        "cvt.rn.f16.f32 b, %2;\n\t"
        "mov.b32 %0, {a, b}; }"
        : "=r"(r) : "f"(lo), "f"(hi));
    return r;
}
__device__ __forceinline__ uint2 h4(float4 v) {
    uint2 u;
    u.x = f16x2(v.x, v.y);
    u.y = f16x2(v.z, v.w);
    return u;
}

// ---------------- LayerNorm + emit fp16 A ------------------------------------
__global__ __launch_bounds__(256) void ln_kernel(const float* __restrict__ x,
                                                 const float* __restrict__ w,
                                                 const float* __restrict__ b) {
    __shared__ float redS[8], redQ[8];
    int row = blockIdx.x;
    int tid = threadIdx.x;
    const float4* xr = (const float4*)(x + (size_t)row * D);
    float4 v0 = xr[tid];
    float4 v1 = xr[tid + 256];
    float s  = v0.x + v0.y + v0.z + v0.w + v1.x + v1.y + v1.z + v1.w;
    float ss = v0.x*v0.x + v0.y*v0.y + v0.z*v0.z + v0.w*v0.w
             + v1.x*v1.x + v1.y*v1.y + v1.z*v1.z + v1.w*v1.w;
    #pragma unroll
    for (int o = 16; o; o >>= 1) {
        s  += __shfl_xor_sync(0xFFFFFFFFu, s, o);
        ss += __shfl_xor_sync(0xFFFFFFFFu, ss, o);
    }
    int wid = tid >> 5;
    if ((tid & 31) == 0) { redS[wid] = s; redQ[wid] = ss; }
    __syncthreads();
    float ts = 0.f, tq = 0.f;
    #pragma unroll
    for (int i = 0; i < 8; i++) { ts += redS[i]; tq += redQ[i]; }
    float mean = ts * (1.0f / D);
    float var  = tq * (1.0f / D) - mean * mean;
    float r = 1.0f / sqrtf(var + LN_EPS);

    const float4* wr = (const float4*)w;
    const float4* br = (const float4*)b;
    float4 w0 = wr[tid], w1 = wr[tid + 256];
    float4 b0 = br[tid], b1 = br[tid + 256];
    float4 o0, o1;
    o0.x = (v0.x - mean) * r * w0.x + b0.x;
    o0.y = (v0.y - mean) * r * w0.y + b0.y;
    o0.z = (v0.z - mean) * r * w0.z + b0.z;
    o0.w = (v0.w - mean) * r * w0.w + b0.w;
    o1.x = (v1.x - mean) * r * w1.x + b1.x;
    o1.y = (v1.y - mean) * r * w1.y + b1.y;
    o1.z = (v1.z - mean) * r * w1.z + b1.z;
    o1.w = (v1.w - mean) * r * w1.w + b1.w;
    float4* outr = (float4*)(g_normed + (size_t)row * D);
    outr[tid] = o0;
    outr[tid + 256] = o1;

    uint2* arow = (uint2*)(g_Ah + (size_t)row * (D / 2));
    arow[tid] = h4(o0);
    arow[tid + 256] = h4(o1);
}

// ---------------- weight convert: fp16 W -------------------------------------
__global__ __launch_bounds__(256) void conv_w_kernel(const float* __restrict__ wq,
                                                     const float* __restrict__ wk,
                                                     const float* __restrict__ wv) {
    int j = blockIdx.x;                    // weight row (output feature)
    int wsel = blockIdx.y;                 // 0..2
    const float* W = (wsel == 0) ? wq : (wsel == 1) ? wk : wv;
    uint2* dst = (uint2*)(g_Wh + (size_t)wsel * ((size_t)D * D / 2) + (size_t)j * (D / 2));
    const float4* src = (const float4*)(W + (size_t)j * D);
    int tid = threadIdx.x;
    dst[tid] = h4(src[tid]);
    dst[tid + 256] = h4(src[tid + 256]);
}

// ---------------- QKV GEMM via mma.sync fp16 m16n8k16 ------------------------
// q,k written as fp16 (consumed by scores mma); v written fp32 (attended).
__global__ __launch_bounds__(256, 2) void qkv_mma_kernel(const float* __restrict__ bq,
                                                         const float* __restrict__ bk,
                                                         const float* __restrict__ bv) {
    extern __shared__ __align__(128) char sm[];
    uint32_t sbase = smem_u32(sm);

    int tid = threadIdx.x;
    int lane = tid & 31;
    int wid = tid >> 5;
    int warp_m = wid >> 2;        // 0..1  -> 64-row slab
    int warp_n = wid & 3;         // 0..3  -> 32-col slab
    int bx = blockIdx.x;          // N tile
    int by = blockIdx.y;          // M tile
    int bz = blockIdx.z;          // q/k/v

    const float* bias = (bz == 0) ? bq : (bz == 1) ? bk : bv;
    const char* Abase = (const char*)g_Ah;                                     // row stride 4096 B
    const char* Bbase = (const char*)(g_Wh + (size_t)bz * ((size_t)D * D / 2)); // row stride 4096 B

    auto load_stage = [&](int st, int j) {
        size_t koff = (size_t)j * 128;     // 64 fp16 = 128 B per iter
        uint32_t sA = sbase + st * GSTAGE_BYTES;
        uint32_t sB = sA + 16384;
        #pragma unroll
        for (int i = 0; i < 4; i++) {
            int idx = tid + i * 256;
            int row = idx >> 3;
            int c16 = idx & 7;
            uint32_t dst = sA + row * 128 + ((c16 ^ (row & 7)) << 4);
            cp16(dst, Abase + (size_t)(by * GBM + row) * 4096 + koff + c16 * 16);
        }
        #pragma unroll
        for (int i = 0; i < 4; i++) {
            int idx = tid + i * 256;
            int row = idx >> 3;
            int c16 = idx & 7;
            uint32_t dst = sB + row * 128 + ((c16 ^ (row & 7)) << 4);
            cp16(dst, Bbase + (size_t)(bx * GBN + row) * 4096 + koff + c16 * 16);
        }
    };

    float acc[4][4][4];
    #pragma unroll
    for (int mf = 0; mf < 4; mf++)
        #pragma unroll
        for (int nf = 0; nf < 4; nf++)
            #pragma unroll
            for (int q = 0; q < 4; q++) acc[mf][nf][q] = 0.f;

    load_stage(0, 0);
    cp_commit();
    load_stage(1, 1);
    cp_commit();

    int arow_off = warp_m * 64 + (lane & 15);
    int brow_off = warp_n * 32 + (lane & 15);
    int khalf = lane >> 4;
    int swz_x = lane & 7;

    for (int it = 0; it < KITERS; it++) {
        cp_wait<1>();
        __syncthreads();
        if (it + 2 < KITERS) load_stage((it + 2) % GSTAGES, it + 2);
        cp_commit();

        uint32_t sA = sbase + (it % GSTAGES) * GSTAGE_BYTES;
        uint32_t sB = sA + 16384;

        #pragma unroll
        for (int ks = 0; ks < 4; ks++) {
            uint32_t swz = (uint32_t)(((ks * 2 + khalf) ^ swz_x) << 4);
            uint32_t a[4][4];
            uint32_t bf[4][2];
            #pragma unroll
            for (int mf = 0; mf < 4; mf++) {
                uint32_t addr = sA + (uint32_t)(arow_off + mf * 16) * 128 + swz;
                LDSM4(a[mf][0], a[mf][1], a[mf][2], a[mf][3], addr);
            }
            #pragma unroll
            for (int nf2 = 0; nf2 < 2; nf2++) {
                uint32_t r0, r1, r2, r3;
                uint32_t addr = sB + (uint32_t)(brow_off + nf2 * 16) * 128 + swz;
                LDSM4(r0, r1, r2, r3, addr);
                bf[nf2 * 2 + 0][0] = r0; bf[nf2 * 2 + 1][0] = r1;
                bf[nf2 * 2 + 0][1] = r2; bf[nf2 * 2 + 1][1] = r3;
            }
            #pragma unroll
            for (int mf = 0; mf < 4; mf++)
                #pragma unroll
                for (int nf = 0; nf < 4; nf++)
                    MMA16816(acc[mf][nf], a[mf], bf[nf][0], bf[nf][1]);
        }
        __syncthreads();
    }

    // epilogue: bias + store (q,k as packed fp16; v as fp32)
    int row_base = by * GBM + warp_m * 64 + (lane >> 2);
    int col_base = bx * GBN + warp_n * 32 + 2 * (lane & 3);   // even
    if (bz < 2) {
        uint32_t* Ch = (bz == 0) ? g_qh : g_kh;
        #pragma unroll
        for (int nf = 0; nf < 4; nf++) {
            int c = col_base + nf * 8;
            float b0 = bias[c], b1 = bias[c + 1];
            #pragma unroll
            for (int mf = 0; mf < 4; mf++) {
                int r0 = row_base + mf * 16;
                Ch[(size_t)r0 * (D / 2) + (c >> 1)] =
                    f16x2(acc[mf][nf][0] + b0, acc[mf][nf][1] + b1);
                Ch[(size_t)(r0 + 8) * (D / 2) + (c >> 1)] =
                    f16x2(acc[mf][nf][2] + b0, acc[mf][nf][3] + b1);
            }
        }
    } else {
        #pragma unroll
        for (int nf = 0; nf < 4; nf++) {
            int c = col_base + nf * 8;
            float b0 = bias[c], b1 = bias[c + 1];
            #pragma unroll
            for (int mf = 0; mf < 4; mf++) {
                int r0 = row_base + mf * 16;
                float2 v0 = make_float2(acc[mf][nf][0] + b0, acc[mf][nf][1] + b1);
                float2 v1 = make_float2(acc[mf][nf][2] + b0, acc[mf][nf][3] + b1);
                *(float2*)(g_v + (size_t)r0 * D + c) = v0;
                *(float2*)(g_v + (size_t)(r0 + 8) * D + c) = v1;
            }
        }
    }
}

// ---------------- scores via fp16 mma: S_part[ks][b] = q.k over K chunk ------
// grid (4, 64), 128 threads (4 warps); warp w computes rows w*16..w*16+15 x 64
__global__ __launch_bounds__(128) void scores_mma_kernel() {
    __shared__ __align__(128) char sm[3 * 16384];     // 3 stages x (Q 8KB + K 8KB)
    uint32_t sbase = smem_u32(sm);
    int ks = blockIdx.x;
    int b = blockIdx.y;
    int tid = threadIdx.x;
    int lane = tid & 31;
    int w = tid >> 5;

    const char* Qb = (const char*)g_qh + (size_t)b * NA * 4096 + (size_t)ks * (SCORE_KCHUNK * 2);
    const char* Kb = (const char*)g_kh + (size_t)b * NA * 4096 + (size_t)ks * (SCORE_KCHUNK * 2);

    auto load_stage = [&](int st, int j) {
        size_t koff = (size_t)j * 128;     // 64 fp16 per iter
        uint32_t sQ = sbase + st * 16384;
        uint32_t sK = sQ + 8192;
        #pragma unroll
        for (int i = 0; i < 4; i++) {
            int idx = tid + i * 128;       // 0..511
            int row = idx >> 3;            // 0..63
            int c16 = idx & 7;
            uint32_t dst = sQ + row * 128 + ((c16 ^ (row & 7)) << 4);
            cp16(dst, Qb + (size_t)row * 4096 + koff + c16 * 16);
        }
        #pragma unroll
        for (int i = 0; i < 4; i++) {
            int idx = tid + i * 128;
            int row = idx >> 3;
            int c16 = idx & 7;
            uint32_t dst = sK + row * 128 + ((c16 ^ (row & 7)) << 4);
            cp16(dst, Kb + (size_t)row * 4096 + koff + c16 * 16);
        }
    };

    float acc[8][4];
    #pragma unroll
    for (int nf = 0; nf < 8; nf++)
        #pragma unroll
        for (int q = 0; q < 4; q++) acc[nf][q] = 0.f;

    load_stage(0, 0);
    cp_commit();
    load_stage(1, 1);
    cp_commit();

    int arow_off = w * 16 + (lane & 15);
    int brow_off = lane & 15;
    int khalf = lane >> 4;
    int swz_x = lane & 7;
    const int NIT = SCORE_KCHUNK / 64;     // 8

    for (int it = 0; it < NIT; it++) {
        cp_wait<1>();
        __syncthreads();
        if (it + 2 < NIT) load_stage((it + 2) % 3, it + 2);
        cp_commit();

        uint32_t sQ = sbase + (it % 3) * 16384;
        uint32_t sK = sQ + 8192;

        #pragma unroll
        for (int g = 0; g < 4; g++) {
            uint32_t swz = (uint32_t)(((g * 2 + khalf) ^ swz_x) << 4);
            uint32_t a[4];
            LDSM4(a[0], a[1], a[2], a[3], sQ + (uint32_t)arow_off * 128 + swz);
            uint32_t bf[8][2];
            #pragma unroll
            for (int nf2 = 0; nf2 < 4; nf2++) {
                uint32_t r0, r1, r2, r3;
                LDSM4(r0, r1, r2, r3, sK + (uint32_t)(brow_off + nf2 * 16) * 128 + swz);
                bf[nf2 * 2 + 0][0] = r0; bf[nf2 * 2 + 1][0] = r1;
                bf[nf2 * 2 + 0][1] = r2; bf[nf2 * 2 + 1][1] = r3;
            }
            #pragma unroll
            for (int nf = 0; nf < 8; nf++)
                MMA16816(acc[nf], a, bf[nf][0], bf[nf][1]);
        }
        __syncthreads();
    }

    float* dst = g_spart + ((size_t)ks * BATCH + b) * 4096;
    int rrow = w * 16 + (lane >> 2);
    int ccol = 2 * (lane & 3);
    #pragma unroll
    for (int nf = 0; nf < 8; nf++) {
        int c = nf * 8 + ccol;
        dst[rrow * 64 + c] = acc[nf][0];
        dst[rrow * 64 + c + 1] = acc[nf][1];
        dst[(rrow + 8) * 64 + c] = acc[nf][2];
        dst[(rrow + 8) * 64 + c + 1] = acc[nf][3];
    }
}

// ---------------- Sinkhorn (sums partials, applies 1/sqrt(D)) ---------------
__global__ __launch_bounds__(1024) void sinkhorn_kernel(float* __restrict__ attn_out) {
    int b = blockIdx.x;
    __shared__ float m[64][65];
    int tid = threadIdx.x;
    const float invS = 1.0f / 45.254833995939045f;
    const float* p0 = g_spart + (size_t)b * 4096;
    const size_t pstride = (size_t)BATCH * 4096;
    for (int i = tid; i < 4096; i += 1024) {
        float v = p0[i] + p0[i + pstride] + p0[i + 2 * pstride] + p0[i + 3 * pstride];
        m[i >> 6][i & 63] = v * invS;
    }
    __syncthreads();
    int w = tid >> 5, lane = tid & 31;
    for (int it = 0; it < SINKHORN_ITERS; it++) {
        #pragma unroll
        for (int rr = 0; rr < 2; rr++) {
            int r = w * 2 + rr;
            float x0 = m[r][lane], x1 = m[r][lane + 32];
            float mx = fmaxf(x0, x1);
            #pragma unroll
            for (int o = 16; o; o >>= 1) mx = fmaxf(mx, __shfl_xor_sync(0xFFFFFFFFu, mx, o));
            float s = expf(x0 - mx) + expf(x1 - mx);
            #pragma unroll
            for (int o = 16; o; o >>= 1) s += __shfl_xor_sync(0xFFFFFFFFu, s, o);
            float lse = mx + logf(s);
            m[r][lane] = x0 - lse;
            m[r][lane + 32] = x1 - lse;
        }
        __syncthreads();
        #pragma unroll
        for (int cc = 0; cc < 2; cc++) {
            int c = w * 2 + cc;
            float x0 = m[lane][c], x1 = m[lane + 32][c];
            float mx = fmaxf(x0, x1);
            #pragma unroll
            for (int o = 16; o; o >>= 1) mx = fmaxf(mx, __shfl_xor_sync(0xFFFFFFFFu, mx, o));
            float s = expf(x0 - mx) + expf(x1 - mx);
            #pragma unroll
            for (int o = 16; o; o >>= 1) s += __shfl_xor_sync(0xFFFFFFFFu, s, o);
            float lse = mx + logf(s);
            m[lane][c] = x0 - lse;
            m[lane + 32][c] = x1 - lse;
        }
        __syncthreads();
    }
    for (int i = tid; i < 4096; i += 1024) {
        float e = expf(m[i >> 6][i & 63]);
        g_attn[(size_t)b * 4096 + i] = e;
        if (attn_out) attn_out[(size_t)b * 4096 + i] = e;
    }
}

// ---------------- attended = attn @ V, fused mix ----------------------------
__global__ __launch_bounds__(256) void attended_kernel() {
    int d0 = blockIdx.x * 128;
    int b = blockIdx.y;
    __shared__ float attn_s[64][64];
    __shared__ float4 Vs[64][32];
    int tid = threadIdx.x;
    const float* ab = g_attn + (size_t)b * 4096;
    for (int i = tid; i < 4096; i += 256) attn_s[i >> 6][i & 63] = ab[i];
    const float* Vb = g_v + (size_t)b * NA * D;
    {
        int r = tid >> 5;
        int c = tid & 31;
        #pragma unroll
        for (int p = 0; p < 8; p++)
            Vs[r + p * 8][c] = *(const float4*)(Vb + (size_t)(r + p * 8) * D + d0 + c * 4);
    }
    __syncthreads();
    int tx = tid & 31, ty = tid >> 5;
    float4 acc[8];
    #pragma unroll
    for (int i = 0; i < 8; i++) acc[i] = make_float4(0.f, 0.f, 0.f, 0.f);
    for (int mm = 0; mm < 64; mm++) {
        float4 v4 = Vs[mm][tx];
        #pragma unroll
        for (int i = 0; i < 8; i++) {
            float a = attn_s[ty * 8 + i][mm];
            acc[i].x += a * v4.x;
            acc[i].y += a * v4.y;
            acc[i].z += a * v4.z;
            acc[i].w += a * v4.w;
        }
    }
    #pragma unroll
    for (int i = 0; i < 8; i++) {
        int n = ty * 8 + i;
        size_t off = ((size_t)(b * 64 + n)) * D + d0 + tx * 4;
        float4 nm = *(const float4*)(g_normed + off);
        float4 o;
        o.x = ID_PRESERVE * nm.x + (1.0f - ID_PRESERVE) * acc[i].x;
        o.y = ID_PRESERVE * nm.y + (1.0f - ID_PRESERVE) * acc[i].y;
        o.z = ID_PRESERVE * nm.z + (1.0f - ID_PRESERVE) * acc[i].z;
        o.w = ID_PRESERVE * nm.w + (1.0f - ID_PRESERVE) * acc[i].w;
        *(float4*)(g_mixed + off) = o;
    }
}

// ---------------- epilogue ---------------------------------------------------
__global__ __launch_bounds__(256) void epilogue_kernel(const float* __restrict__ x,
                                                       const float* __restrict__ biases,
                                                       const float* __restrict__ scales,
                                                       float* __restrict__ out) {
    __shared__ float red[8];
    int row = blockIdx.x;
    int n = row & 63;
    int tid = threadIdx.x;
    float sc = scales[n];
    const float4* mr = (const float4*)(g_mixed + (size_t)row * D);
    const float4* br = (const float4*)(biases + (size_t)n * D);
    float4 m0 = mr[tid], m1 = mr[tid + 256];
    float4 b0 = br[tid], b1 = br[tid + 256];
    float4 s0, s1;
    s0.x = (m0.x + b0.x) * sc; s0.y = (m0.y + b0.y) * sc;
    s0.z = (m0.z + b0.z) * sc; s0.w = (m0.w + b0.w) * sc;
    s1.x = (m1.x + b1.x) * sc; s1.y = (m1.y + b1.y) * sc;
    s1.z = (m1.z + b1.z) * sc; s1.w = (m1.w + b1.w) * sc;
    float ss = s0.x*s0.x + s0.y*s0.y + s0.z*s0.z + s0.w*s0.w
             + s1.x*s1.x + s1.y*s1.y + s1.z*s1.z + s1.w*s1.w;
    #pragma unroll
    for (int o = 16; o; o >>= 1) ss += __shfl_xor_sync(0xFFFFFFFFu, ss, o);
    if ((tid & 31) == 0) red[tid >> 5] = ss;
    __syncthreads();
    float tot = 0.f;
    #pragma unroll
    for (int i = 0; i < 8; i++) tot += red[i];
    float norm = sqrtf(tot);
    float inv = 1.0f / fmaxf(1.0f, norm / SIGNAL_BOUND);
    const float4* xr = (const float4*)(x + (size_t)row * D);
    float4 x0 = xr[tid], x1 = xr[tid + 256];
    float4 o0, o1;
    o0.x = x0.x + s0.x * inv; o0.y = x0.y + s0.y * inv;
    o0.z = x0.z + s0.z * inv; o0.w = x0.w + s0.w * inv;
    o1.x = x1.x + s1.x * inv; o1.y = x1.y + s1.y * inv;
    o1.z = x1.z + s1.z * inv; o1.w = x1.w + s1.w * inv;
    float4* outr = (float4*)(out + (size_t)row * D);
    outr[tid] = o0;
    outr[tid + 256] = o1;
}

// ---------------- launch -----------------------------------------------------
extern "C" void kernel_launch(void* const* d_in, const int* in_sizes, int n_in,
                              void* d_out, int out_size) {
    const float* agent_states  = (const float*)d_in[0];
    const float* ln_w          = (const float*)d_in[1];
    const float* ln_b          = (const float*)d_in[2];
    const float* wq            = (const float*)d_in[3];
    const float* bq            = (const float*)d_in[4];
    const float* wk            = (const float*)d_in[5];
    const float* bk            = (const float*)d_in[6];
    const float* wv            = (const float*)d_in[7];
    const float* bv            = (const float*)d_in[8];
    const float* agent_biases  = (const float*)d_in[9];
    const float* scale_factors = (const float*)d_in[10];
    float* out = (float*)d_out;
    float* attn_out = (out_size >= ROWS * D + BATCH * NA * NA) ? (out + (size_t)ROWS * D)
                                                               : nullptr;

    const int DYN_SMEM = GSTAGES * GSTAGE_BYTES;   // 96 KB
    cudaFuncSetAttribute(qkv_mma_kernel, cudaFuncAttributeMaxDynamicSharedMemorySize, DYN_SMEM);

    ln_kernel<<<ROWS, 256>>>(agent_states, ln_w, ln_b);
    conv_w_kernel<<<dim3(D, 3), 256>>>(wq, wk, wv);
    qkv_mma_kernel<<<dim3(D / GBN, ROWS / GBM, 3), 256, DYN_SMEM>>>(bq, bk, bv);
    scores_mma_kernel<<<dim3(SCORE_KSPLIT, BATCH), 128>>>();
    sinkhorn_kernel<<<BATCH, 1024>>>(attn_out);
    attended_kernel<<<dim3(16, BATCH), 256>>>();
    epilogue_kernel<<<ROWS, 256>>>(agent_states, agent_biases, scale_factors, out);
}

// round 15
// speedup vs baseline: 2.4856x; 1.0303x over previous
#include <cuda_runtime.h>
#include <math.h>
#include <stdint.h>

#define D 2048
#define NA 64
#define BATCH 64
#define ROWS (BATCH * NA)        // 4096
#define LN_EPS 1e-5f
#define ID_PRESERVE 0.1f
#define SIGNAL_BOUND 1.0f
#define SINKHORN_ITERS 50

// GEMM: CTA 128x128, fp16 single pass K=2048, BK=64 fp16 (128B rows), 3-stage
#define GBM 128
#define GBN 128
#define KITERS 32                // 2048 / 64
#define GSTAGES 3
#define GSTAGE_BYTES 32768       // A 16KB + B 16KB (128 rows x 128B each)

#define SCORE_KSPLIT 4
#define SCORE_KCHUNK (D / SCORE_KSPLIT)   // 512 elems

// ---------------- scratch (device globals; no allocation allowed) ----------
__device__ float g_mixed[ROWS * D];
__device__ float g_spart[SCORE_KSPLIT * BATCH * NA * NA];
__device__ float g_attn[BATCH * NA * NA];
// fp16 operands stored as packed u32 pairs (no cuda_fp16.h — triggers infra failure)
__device__ uint32_t g_Ah[(size_t)ROWS * D / 2];          // fp16(normed) [4096, 2048]
__device__ uint32_t g_Wh[3ull * D * D / 2];              // 3 x [2048, 2048] fp16
__device__ uint32_t g_qh[(size_t)ROWS * D / 2];          // q in fp16
__device__ uint32_t g_kh[(size_t)ROWS * D / 2];          // k in fp16
__device__ uint32_t g_vh[(size_t)ROWS * D / 2];          // v in fp16

// ---------------- PTX helpers ------------------------------------------------
__device__ __forceinline__ uint32_t smem_u32(const void* p) {
    uint32_t a;
    asm("{ .reg .u64 t; cvta.to.shared.u64 t, %1; cvt.u32.u64 %0, t; }" : "=r"(a) : "l"(p));
    return a;
}
__device__ __forceinline__ void cp16(uint32_t dst, const void* src) {
    asm volatile("cp.async.cg.shared.global [%0], [%1], 16;" :: "r"(dst), "l"(src));
}
__device__ __forceinline__ void cp_commit() { asm volatile("cp.async.commit_group;" ::: "memory"); }
template <int N>
__device__ __forceinline__ void cp_wait() { asm volatile("cp.async.wait_group %0;" :: "n"(N) : "memory"); }

#define LDSM4(r0, r1, r2, r3, addr) \
    asm volatile("ldmatrix.sync.aligned.m8n8.x4.shared.b16 {%0,%1,%2,%3}, [%4];" \
                 : "=r"(r0), "=r"(r1), "=r"(r2), "=r"(r3) : "r"(addr))

#define MMA16816(acc, a, b0r, b1r) \
    asm volatile( \
        "mma.sync.aligned.m16n8k16.row.col.f32.f16.f16.f32 " \
        "{%0,%1,%2,%3}, {%4,%5,%6,%7}, {%8,%9}, {%0,%1,%2,%3};" \
        : "+f"((acc)[0]), "+f"((acc)[1]), "+f"((acc)[2]), "+f"((acc)[3]) \
        : "r"((a)[0]), "r"((a)[1]), "r"((a)[2]), "r"((a)[3]), \
          "r"(b0r), "r"(b1r))

// pack two fp32 -> fp16x2 in a b32 register (pure PTX, no half headers)
__device__ __forceinline__ uint32_t f16x2(float lo, float hi) {
    uint32_t r;
    asm("{ .reg .f16 a, b;\n\t"
        "cvt.rn.f16.f32 a, %1;\n\t"
        "cvt.rn.f16.f32 b, %2;\n\t"
        "mov.b32 %0, {a, b}; }"
        : "=r"(r) : "f"(lo), "f"(hi));
    return r;
}
__device__ __forceinline__ uint2 h4(float4 v) {
    uint2 u;
    u.x = f16x2(v.x, v.y);
    u.y = f16x2(v.z, v.w);
    return u;
}
// unpack fp16x2 -> two fp32
__device__ __forceinline__ float2 h2f2(uint32_t h) {
    float2 f;
    asm("{ .reg .f16 lo, hi;\n\t"
        "mov.b32 {lo, hi}, %2;\n\t"
        "cvt.f32.f16 %0, lo;\n\t"
        "cvt.f32.f16 %1, hi; }"
        : "=f"(f.x), "=f"(f.y) : "r"(h));
    return f;
}
__device__ __forceinline__ float4 h4f4(uint2 u) {
    float2 a = h2f2(u.x), b = h2f2(u.y);
    return make_float4(a.x, a.y, b.x, b.y);
}

// ---------------- prep: LayerNorm->fp16 A, plus fp16 W convert ---------------
// grid: [0, ROWS) = ln rows; [ROWS, ROWS+3*D) = weight rows
__global__ __launch_bounds__(256) void prep_kernel(const float* __restrict__ x,
                                                   const float* __restrict__ w,
                                                   const float* __restrict__ b,
                                                   const float* __restrict__ wq,
                                                   const float* __restrict__ wk,
                                                   const float* __restrict__ wv) {
    __shared__ float redS[8], redQ[8];
    int blk = blockIdx.x;
    int tid = threadIdx.x;
    if (blk >= ROWS) {
        int t = blk - ROWS;
        int wsel = t >> 11;                // t / D
        int j = t & (D - 1);               // t % D
        const float* W = (wsel == 0) ? wq : (wsel == 1) ? wk : wv;
        uint2* dst = (uint2*)(g_Wh + (size_t)wsel * ((size_t)D * D / 2) + (size_t)j * (D / 2));
        const float4* src = (const float4*)(W + (size_t)j * D);
        dst[tid] = h4(src[tid]);
        dst[tid + 256] = h4(src[tid + 256]);
        return;
    }
    int row = blk;
    const float4* xr = (const float4*)(x + (size_t)row * D);
    float4 v0 = xr[tid];
    float4 v1 = xr[tid + 256];
    float s  = v0.x + v0.y + v0.z + v0.w + v1.x + v1.y + v1.z + v1.w;
    float ss = v0.x*v0.x + v0.y*v0.y + v0.z*v0.z + v0.w*v0.w
             + v1.x*v1.x + v1.y*v1.y + v1.z*v1.z + v1.w*v1.w;
    #pragma unroll
    for (int o = 16; o; o >>= 1) {
        s  += __shfl_xor_sync(0xFFFFFFFFu, s, o);
        ss += __shfl_xor_sync(0xFFFFFFFFu, ss, o);
    }
    int wid = tid >> 5;
    if ((tid & 31) == 0) { redS[wid] = s; redQ[wid] = ss; }
    __syncthreads();
    float ts = 0.f, tq = 0.f;
    #pragma unroll
    for (int i = 0; i < 8; i++) { ts += redS[i]; tq += redQ[i]; }
    float mean = ts * (1.0f / D);
    float var  = tq * (1.0f / D) - mean * mean;
    float r = 1.0f / sqrtf(var + LN_EPS);

    const float4* wr = (const float4*)w;
    const float4* br = (const float4*)b;
    float4 w0 = wr[tid], w1 = wr[tid + 256];
    float4 b0 = br[tid], b1 = br[tid + 256];
    float4 o0, o1;
    o0.x = (v0.x - mean) * r * w0.x + b0.x;
    o0.y = (v0.y - mean) * r * w0.y + b0.y;
    o0.z = (v0.z - mean) * r * w0.z + b0.z;
    o0.w = (v0.w - mean) * r * w0.w + b0.w;
    o1.x = (v1.x - mean) * r * w1.x + b1.x;
    o1.y = (v1.y - mean) * r * w1.y + b1.y;
    o1.z = (v1.z - mean) * r * w1.z + b1.z;
    o1.w = (v1.w - mean) * r * w1.w + b1.w;

    uint2* arow = (uint2*)(g_Ah + (size_t)row * (D / 2));
    arow[tid] = h4(o0);
    arow[tid + 256] = h4(o1);
}

// ---------------- QKV GEMM via mma.sync fp16 m16n8k16 ------------------------
// q,k,v all written as packed fp16
__global__ __launch_bounds__(256, 2) void qkv_mma_kernel(const float* __restrict__ bq,
                                                         const float* __restrict__ bk,
                                                         const float* __restrict__ bv) {
    extern __shared__ __align__(128) char sm[];
    uint32_t sbase = smem_u32(sm);

    int tid = threadIdx.x;
    int lane = tid & 31;
    int wid = tid >> 5;
    int warp_m = wid >> 2;
    int warp_n = wid & 3;
    int bx = blockIdx.x;
    int by = blockIdx.y;
    int bz = blockIdx.z;

    const float* bias = (bz == 0) ? bq : (bz == 1) ? bk : bv;
    uint32_t* Ch = (bz == 0) ? g_qh : (bz == 1) ? g_kh : g_vh;
    const char* Abase = (const char*)g_Ah;                                     // row stride 4096 B
    const char* Bbase = (const char*)(g_Wh + (size_t)bz * ((size_t)D * D / 2)); // row stride 4096 B

    auto load_stage = [&](int st, int j) {
        size_t koff = (size_t)j * 128;
        uint32_t sA = sbase + st * GSTAGE_BYTES;
        uint32_t sB = sA + 16384;
        #pragma unroll
        for (int i = 0; i < 4; i++) {
            int idx = tid + i * 256;
            int row = idx >> 3;
            int c16 = idx & 7;
            uint32_t dst = sA + row * 128 + ((c16 ^ (row & 7)) << 4);
            cp16(dst, Abase + (size_t)(by * GBM + row) * 4096 + koff + c16 * 16);
        }
        #pragma unroll
        for (int i = 0; i < 4; i++) {
            int idx = tid + i * 256;
            int row = idx >> 3;
            int c16 = idx & 7;
            uint32_t dst = sB + row * 128 + ((c16 ^ (row & 7)) << 4);
            cp16(dst, Bbase + (size_t)(bx * GBN + row) * 4096 + koff + c16 * 16);
        }
    };

    float acc[4][4][4];
    #pragma unroll
    for (int mf = 0; mf < 4; mf++)
        #pragma unroll
        for (int nf = 0; nf < 4; nf++)
            #pragma unroll
            for (int q = 0; q < 4; q++) acc[mf][nf][q] = 0.f;

    load_stage(0, 0);
    cp_commit();
    load_stage(1, 1);
    cp_commit();

    int arow_off = warp_m * 64 + (lane & 15);
    int brow_off = warp_n * 32 + (lane & 15);
    int khalf = lane >> 4;
    int swz_x = lane & 7;

    for (int it = 0; it < KITERS; it++) {
        cp_wait<1>();
        __syncthreads();
        if (it + 2 < KITERS) load_stage((it + 2) % GSTAGES, it + 2);
        cp_commit();

        uint32_t sA = sbase + (it % GSTAGES) * GSTAGE_BYTES;
        uint32_t sB = sA + 16384;

        #pragma unroll
        for (int ks = 0; ks < 4; ks++) {
            uint32_t swz = (uint32_t)(((ks * 2 + khalf) ^ swz_x) << 4);
            uint32_t a[4][4];
            uint32_t bf[4][2];
            #pragma unroll
            for (int mf = 0; mf < 4; mf++) {
                uint32_t addr = sA + (uint32_t)(arow_off + mf * 16) * 128 + swz;
                LDSM4(a[mf][0], a[mf][1], a[mf][2], a[mf][3], addr);
            }
            #pragma unroll
            for (int nf2 = 0; nf2 < 2; nf2++) {
                uint32_t r0, r1, r2, r3;
                uint32_t addr = sB + (uint32_t)(brow_off + nf2 * 16) * 128 + swz;
                LDSM4(r0, r1, r2, r3, addr);
                bf[nf2 * 2 + 0][0] = r0; bf[nf2 * 2 + 1][0] = r1;
                bf[nf2 * 2 + 0][1] = r2; bf[nf2 * 2 + 1][1] = r3;
            }
            #pragma unroll
            for (int mf = 0; mf < 4; mf++)
                #pragma unroll
                for (int nf = 0; nf < 4; nf++)
                    MMA16816(acc[mf][nf], a[mf], bf[nf][0], bf[nf][1]);
        }
        __syncthreads();
    }

    // epilogue: bias + store packed fp16
    int row_base = by * GBM + warp_m * 64 + (lane >> 2);
    int col_base = bx * GBN + warp_n * 32 + 2 * (lane & 3);   // even
    #pragma unroll
    for (int nf = 0; nf < 4; nf++) {
        int c = col_base + nf * 8;
        float b0 = bias[c], b1 = bias[c + 1];
        #pragma unroll
        for (int mf = 0; mf < 4; mf++) {
            int r0 = row_base + mf * 16;
            Ch[(size_t)r0 * (D / 2) + (c >> 1)] =
                f16x2(acc[mf][nf][0] + b0, acc[mf][nf][1] + b1);
            Ch[(size_t)(r0 + 8) * (D / 2) + (c >> 1)] =
                f16x2(acc[mf][nf][2] + b0, acc[mf][nf][3] + b1);
        }
    }
}

// ---------------- scores via fp16 mma ----------------------------------------
__global__ __launch_bounds__(128) void scores_mma_kernel() {
    __shared__ __align__(128) char sm[3 * 16384];
    uint32_t sbase = smem_u32(sm);
    int ks = blockIdx.x;
    int b = blockIdx.y;
    int tid = threadIdx.x;
    int lane = tid & 31;
    int w = tid >> 5;

    const char* Qb = (const char*)g_qh + (size_t)b * NA * 4096 + (size_t)ks * (SCORE_KCHUNK * 2);
    const char* Kb = (const char*)g_kh + (size_t)b * NA * 4096 + (size_t)ks * (SCORE_KCHUNK * 2);

    auto load_stage = [&](int st, int j) {
        size_t koff = (size_t)j * 128;
        uint32_t sQ = sbase + st * 16384;
        uint32_t sK = sQ + 8192;
        #pragma unroll
        for (int i = 0; i < 4; i++) {
            int idx = tid + i * 128;
            int row = idx >> 3;
            int c16 = idx & 7;
            uint32_t dst = sQ + row * 128 + ((c16 ^ (row & 7)) << 4);
            cp16(dst, Qb + (size_t)row * 4096 + koff + c16 * 16);
        }
        #pragma unroll
        for (int i = 0; i < 4; i++) {
            int idx = tid + i * 128;
            int row = idx >> 3;
            int c16 = idx & 7;
            uint32_t dst = sK + row * 128 + ((c16 ^ (row & 7)) << 4);
            cp16(dst, Kb + (size_t)row * 4096 + koff + c16 * 16);
        }
    };

    float acc[8][4];
    #pragma unroll
    for (int nf = 0; nf < 8; nf++)
        #pragma unroll
        for (int q = 0; q < 4; q++) acc[nf][q] = 0.f;

    load_stage(0, 0);
    cp_commit();
    load_stage(1, 1);
    cp_commit();

    int arow_off = w * 16 + (lane & 15);
    int brow_off = lane & 15;
    int khalf = lane >> 4;
    int swz_x = lane & 7;
    const int NIT = SCORE_KCHUNK / 64;     // 8

    for (int it = 0; it < NIT; it++) {
        cp_wait<1>();
        __syncthreads();
        if (it + 2 < NIT) load_stage((it + 2) % 3, it + 2);
        cp_commit();

        uint32_t sQ = sbase + (it % 3) * 16384;
        uint32_t sK = sQ + 8192;

        #pragma unroll
        for (int g = 0; g < 4; g++) {
            uint32_t swz = (uint32_t)(((g * 2 + khalf) ^ swz_x) << 4);
            uint32_t a[4];
            LDSM4(a[0], a[1], a[2], a[3], sQ + (uint32_t)arow_off * 128 + swz);
            uint32_t bf[8][2];
            #pragma unroll
            for (int nf2 = 0; nf2 < 4; nf2++) {
                uint32_t r0, r1, r2, r3;
                LDSM4(r0, r1, r2, r3, sK + (uint32_t)(brow_off + nf2 * 16) * 128 + swz);
                bf[nf2 * 2 + 0][0] = r0; bf[nf2 * 2 + 1][0] = r1;
                bf[nf2 * 2 + 0][1] = r2; bf[nf2 * 2 + 1][1] = r3;
            }
            #pragma unroll
            for (int nf = 0; nf < 8; nf++)
                MMA16816(acc[nf], a, bf[nf][0], bf[nf][1]);
        }
        __syncthreads();
    }

    float* dst = g_spart + ((size_t)ks * BATCH + b) * 4096;
    int rrow = w * 16 + (lane >> 2);
    int ccol = 2 * (lane & 3);
    #pragma unroll
    for (int nf = 0; nf < 8; nf++) {
        int c = nf * 8 + ccol;
        dst[rrow * 64 + c] = acc[nf][0];
        dst[rrow * 64 + c + 1] = acc[nf][1];
        dst[(rrow + 8) * 64 + c] = acc[nf][2];
        dst[(rrow + 8) * 64 + c + 1] = acc[nf][3];
    }
}

// ---------------- Sinkhorn (sums partials, applies 1/sqrt(D)) ---------------
__global__ __launch_bounds__(1024) void sinkhorn_kernel(float* __restrict__ attn_out) {
    int b = blockIdx.x;
    __shared__ float m[64][65];
    int tid = threadIdx.x;
    const float invS = 1.0f / 45.254833995939045f;
    const float* p0 = g_spart + (size_t)b * 4096;
    const size_t pstride = (size_t)BATCH * 4096;
    for (int i = tid; i < 4096; i += 1024) {
        float v = p0[i] + p0[i + pstride] + p0[i + 2 * pstride] + p0[i + 3 * pstride];
        m[i >> 6][i & 63] = v * invS;
    }
    __syncthreads();
    int w = tid >> 5, lane = tid & 31;
    for (int it = 0; it < SINKHORN_ITERS; it++) {
        #pragma unroll
        for (int rr = 0; rr < 2; rr++) {
            int r = w * 2 + rr;
            float x0 = m[r][lane], x1 = m[r][lane + 32];
            float mx = fmaxf(x0, x1);
            #pragma unroll
            for (int o = 16; o; o >>= 1) mx = fmaxf(mx, __shfl_xor_sync(0xFFFFFFFFu, mx, o));
            float s = expf(x0 - mx) + expf(x1 - mx);
            #pragma unroll
            for (int o = 16; o; o >>= 1) s += __shfl_xor_sync(0xFFFFFFFFu, s, o);
            float lse = mx + logf(s);
            m[r][lane] = x0 - lse;
            m[r][lane + 32] = x1 - lse;
        }
        __syncthreads();
        #pragma unroll
        for (int cc = 0; cc < 2; cc++) {
            int c = w * 2 + cc;
            float x0 = m[lane][c], x1 = m[lane + 32][c];
            float mx = fmaxf(x0, x1);
            #pragma unroll
            for (int o = 16; o; o >>= 1) mx = fmaxf(mx, __shfl_xor_sync(0xFFFFFFFFu, mx, o));
            float s = expf(x0 - mx) + expf(x1 - mx);
            #pragma unroll
            for (int o = 16; o; o >>= 1) s += __shfl_xor_sync(0xFFFFFFFFu, s, o);
            float lse = mx + logf(s);
            m[lane][c] = x0 - lse;
            m[lane + 32][c] = x1 - lse;
        }
        __syncthreads();
    }
    for (int i = tid; i < 4096; i += 1024) {
        float e = expf(m[i >> 6][i & 63]);
        g_attn[(size_t)b * 4096 + i] = e;
        if (attn_out) attn_out[(size_t)b * 4096 + i] = e;
    }
}

// ---------------- attended = attn @ V(fp16), fused mix with fp16 normed ------
__global__ __launch_bounds__(256) void attended_kernel() {
    int d0 = blockIdx.x * 128;
    int b = blockIdx.y;
    __shared__ float attn_s[64][64];
    __shared__ float4 Vs[64][32];
    int tid = threadIdx.x;
    const float* ab = g_attn + (size_t)b * 4096;
    for (int i = tid; i < 4096; i += 256) attn_s[i >> 6][i & 63] = ab[i];
    const uint2* Vb = (const uint2*)g_vh;    // row = (b*64+m): index row*(D/4) + d/4
    {
        int r = tid >> 5;
        int c = tid & 31;
        #pragma unroll
        for (int p = 0; p < 8; p++) {
            int row = b * 64 + r + p * 8;
            uint2 vh = Vb[(size_t)row * (D / 4) + (d0 >> 2) + c];
            Vs[r + p * 8][c] = h4f4(vh);
        }
    }
    __syncthreads();
    int tx = tid & 31, ty = tid >> 5;
    float4 acc[8];
    #pragma unroll
    for (int i = 0; i < 8; i++) acc[i] = make_float4(0.f, 0.f, 0.f, 0.f);
    for (int mm = 0; mm < 64; mm++) {
        float4 v4 = Vs[mm][tx];
        #pragma unroll
        for (int i = 0; i < 8; i++) {
            float a = attn_s[ty * 8 + i][mm];
            acc[i].x += a * v4.x;
            acc[i].y += a * v4.y;
            acc[i].z += a * v4.z;
            acc[i].w += a * v4.w;
        }
    }
    const uint2* Ab = (const uint2*)g_Ah;
    #pragma unroll
    for (int i = 0; i < 8; i++) {
        int n = ty * 8 + i;
        int row = b * 64 + n;
        float4 nm = h4f4(Ab[(size_t)row * (D / 4) + (d0 >> 2) + tx]);
        size_t off = (size_t)row * D + d0 + tx * 4;
        float4 o;
        o.x = ID_PRESERVE * nm.x + (1.0f - ID_PRESERVE) * acc[i].x;
        o.y = ID_PRESERVE * nm.y + (1.0f - ID_PRESERVE) * acc[i].y;
        o.z = ID_PRESERVE * nm.z + (1.0f - ID_PRESERVE) * acc[i].z;
        o.w = ID_PRESERVE * nm.w + (1.0f - ID_PRESERVE) * acc[i].w;
        *(float4*)(g_mixed + off) = o;
    }
}

// ---------------- epilogue ---------------------------------------------------
__global__ __launch_bounds__(256) void epilogue_kernel(const float* __restrict__ x,
                                                       const float* __restrict__ biases,
                                                       const float* __restrict__ scales,
                                                       float* __restrict__ out) {
    __shared__ float red[8];
    int row = blockIdx.x;
    int n = row & 63;
    int tid = threadIdx.x;
    float sc = scales[n];
    const float4* mr = (const float4*)(g_mixed + (size_t)row * D);
    const float4* br = (const float4*)(biases + (size_t)n * D);
    float4 m0 = mr[tid], m1 = mr[tid + 256];
    float4 b0 = br[tid], b1 = br[tid + 256];
    float4 s0, s1;
    s0.x = (m0.x + b0.x) * sc; s0.y = (m0.y + b0.y) * sc;
    s0.z = (m0.z + b0.z) * sc; s0.w = (m0.w + b0.w) * sc;
    s1.x = (m1.x + b1.x) * sc; s1.y = (m1.y + b1.y) * sc;
    s1.z = (m1.z + b1.z) * sc; s1.w = (m1.w + b1.w) * sc;
    float ss = s0.x*s0.x + s0.y*s0.y + s0.z*s0.z + s0.w*s0.w
             + s1.x*s1.x + s1.y*s1.y + s1.z*s1.z + s1.w*s1.w;
    #pragma unroll
    for (int o = 16; o; o >>= 1) ss += __shfl_xor_sync(0xFFFFFFFFu, ss, o);
    if ((tid & 31) == 0) red[tid >> 5] = ss;
    __syncthreads();
    float tot = 0.f;
    #pragma unroll
    for (int i = 0; i < 8; i++) tot += red[i];
    float norm = sqrtf(tot);
    float inv = 1.0f / fmaxf(1.0f, norm / SIGNAL_BOUND);
    const float4* xr = (const float4*)(x + (size_t)row * D);
    float4 x0 = xr[tid], x1 = xr[tid + 256];
    float4 o0, o1;
    o0.x = x0.x + s0.x * inv; o0.y = x0.y + s0.y * inv;
    o0.z = x0.z + s0.z * inv; o0.w = x0.w + s0.w * inv;
    o1.x = x1.x + s1.x * inv; o1.y = x1.y + s1.y * inv;
    o1.z = x1.z + s1.z * inv; o1.w = x1.w + s1.w * inv;
    float4* outr = (float4*)(out + (size_t)row * D);
    outr[tid] = o0;
    outr[tid + 256] = o1;
}

// ---------------- launch -----------------------------------------------------
extern "C" void kernel_launch(void* const* d_in, const int* in_sizes, int n_in,
                              void* d_out, int out_size) {
    const float* agent_states  = (const float*)d_in[0];
    const float* ln_w          = (const float*)d_in[1];
    const float* ln_b          = (const float*)d_in[2];
    const float* wq            = (const float*)d_in[3];
    const float* bq            = (const float*)d_in[4];
    const float* wk            = (const float*)d_in[5];
    const float* bk            = (const float*)d_in[6];
    const float* wv            = (const float*)d_in[7];
    const float* bv            = (const float*)d_in[8];
    const float* agent_biases  = (const float*)d_in[9];
    const float* scale_factors = (const float*)d_in[10];
    float* out = (float*)d_out;
    float* attn_out = (out_size >= ROWS * D + BATCH * NA * NA) ? (out + (size_t)ROWS * D)
                                                               : nullptr;

    const int DYN_SMEM = GSTAGES * GSTAGE_BYTES;   // 96 KB
    cudaFuncSetAttribute(qkv_mma_kernel, cudaFuncAttributeMaxDynamicSharedMemorySize, DYN_SMEM);

    prep_kernel<<<ROWS + 3 * D, 256>>>(agent_states, ln_w, ln_b, wq, wk, wv);
    qkv_mma_kernel<<<dim3(D / GBN, ROWS / GBM, 3), 256, DYN_SMEM>>>(bq, bk, bv);
    scores_mma_kernel<<<dim3(SCORE_KSPLIT, BATCH), 128>>>();
    sinkhorn_kernel<<<BATCH, 1024>>>(attn_out);
    attended_kernel<<<dim3(16, BATCH), 256>>>();
    epilogue_kernel<<<ROWS, 256>>>(agent_states, agent_biases, scale_factors, out);
}

// round 16
// speedup vs baseline: 2.6979x; 1.0854x over previous
#include <cuda_runtime.h>
#include <math.h>
#include <stdint.h>

#define D 2048
#define NA 64
#define BATCH 64
#define ROWS (BATCH * NA)        // 4096
#define LN_EPS 1e-5f
#define ID_PRESERVE 0.1f
#define SIGNAL_BOUND 1.0f
#define SINKHORN_ITERS 50

// GEMM: CTA 128x128, fp16 single pass K=2048, BK=64 fp16 (128B rows), 3-stage
#define GBM 128
#define GBN 128
#define KITERS 32                // 2048 / 64
#define GSTAGES 3
#define GSTAGE_BYTES 32768       // A 16KB + B 16KB (128 rows x 128B each)

#define SCORE_KSPLIT 4
#define SCORE_KCHUNK (D / SCORE_KSPLIT)   // 512 elems

// ---------------- scratch (device globals; no allocation allowed) ----------
__device__ float g_mixed[ROWS * D];
__device__ float g_spart[SCORE_KSPLIT * BATCH * NA * NA];
__device__ float g_attn[BATCH * NA * NA];
// fp16 operands stored as packed u32 pairs (no cuda_fp16.h — triggers infra failure)
__device__ uint32_t g_Ah[(size_t)ROWS * D / 2];          // fp16(normed) [4096, 2048]
__device__ uint32_t g_Wh[3ull * D * D / 2];              // 3 x [2048, 2048] fp16
__device__ uint32_t g_qh[(size_t)ROWS * D / 2];          // q in fp16
__device__ uint32_t g_kh[(size_t)ROWS * D / 2];          // k in fp16
__device__ uint32_t g_vh[(size_t)ROWS * D / 2];          // v in fp16

// ---------------- PTX helpers ------------------------------------------------
__device__ __forceinline__ uint32_t smem_u32(const void* p) {
    uint32_t a;
    asm("{ .reg .u64 t; cvta.to.shared.u64 t, %1; cvt.u32.u64 %0, t; }" : "=r"(a) : "l"(p));
    return a;
}
__device__ __forceinline__ void cp16(uint32_t dst, const void* src) {
    asm volatile("cp.async.cg.shared.global [%0], [%1], 16;" :: "r"(dst), "l"(src));
}
__device__ __forceinline__ void cp_commit() { asm volatile("cp.async.commit_group;" ::: "memory"); }
template <int N>
__device__ __forceinline__ void cp_wait() { asm volatile("cp.async.wait_group %0;" :: "n"(N) : "memory"); }

#define LDSM4(r0, r1, r2, r3, addr) \
    asm volatile("ldmatrix.sync.aligned.m8n8.x4.shared.b16 {%0,%1,%2,%3}, [%4];" \
                 : "=r"(r0), "=r"(r1), "=r"(r2), "=r"(r3) : "r"(addr))

#define MMA16816(acc, a, b0r, b1r) \
    asm volatile( \
        "mma.sync.aligned.m16n8k16.row.col.f32.f16.f16.f32 " \
        "{%0,%1,%2,%3}, {%4,%5,%6,%7}, {%8,%9}, {%0,%1,%2,%3};" \
        : "+f"((acc)[0]), "+f"((acc)[1]), "+f"((acc)[2]), "+f"((acc)[3]) \
        : "r"((a)[0]), "r"((a)[1]), "r"((a)[2]), "r"((a)[3]), \
          "r"(b0r), "r"(b1r))

// pack two fp32 -> fp16x2 in a b32 register (pure PTX, no half headers)
__device__ __forceinline__ uint32_t f16x2(float lo, float hi) {
    uint32_t r;
    asm("{ .reg .f16 a, b;\n\t"
        "cvt.rn.f16.f32 a, %1;\n\t"
        "cvt.rn.f16.f32 b, %2;\n\t"
        "mov.b32 %0, {a, b}; }"
        : "=r"(r) : "f"(lo), "f"(hi));
    return r;
}
__device__ __forceinline__ uint2 h4(float4 v) {
    uint2 u;
    u.x = f16x2(v.x, v.y);
    u.y = f16x2(v.z, v.w);
    return u;
}
// unpack fp16x2 -> two fp32
__device__ __forceinline__ float2 h2f2(uint32_t h) {
    float2 f;
    asm("{ .reg .f16 lo, hi;\n\t"
        "mov.b32 {lo, hi}, %2;\n\t"
        "cvt.f32.f16 %0, lo;\n\t"
        "cvt.f32.f16 %1, hi; }"
        : "=f"(f.x), "=f"(f.y) : "r"(h));
    return f;
}
__device__ __forceinline__ float4 h4f4(uint2 u) {
    float2 a = h2f2(u.x), b = h2f2(u.y);
    return make_float4(a.x, a.y, b.x, b.y);
}
// base-2 exp/log via MUFU
__device__ __forceinline__ float ex2(float x) {
    float y;
    asm("ex2.approx.f32 %0, %1;" : "=f"(y) : "f"(x));
    return y;
}
__device__ __forceinline__ float lg2(float x) {
    float y;
    asm("lg2.approx.f32 %0, %1;" : "=f"(y) : "f"(x));
    return y;
}

// ---------------- prep: LayerNorm->fp16 A, plus fp16 W convert ---------------
// grid: [0, ROWS) = ln rows; [ROWS, ROWS+3*D) = weight rows
__global__ __launch_bounds__(256) void prep_kernel(const float* __restrict__ x,
                                                   const float* __restrict__ w,
                                                   const float* __restrict__ b,
                                                   const float* __restrict__ wq,
                                                   const float* __restrict__ wk,
                                                   const float* __restrict__ wv) {
    __shared__ float redS[8], redQ[8];
    int blk = blockIdx.x;
    int tid = threadIdx.x;
    if (blk >= ROWS) {
        int t = blk - ROWS;
        int wsel = t >> 11;                // t / D
        int j = t & (D - 1);               // t % D
        const float* W = (wsel == 0) ? wq : (wsel == 1) ? wk : wv;
        uint2* dst = (uint2*)(g_Wh + (size_t)wsel * ((size_t)D * D / 2) + (size_t)j * (D / 2));
        const float4* src = (const float4*)(W + (size_t)j * D);
        dst[tid] = h4(src[tid]);
        dst[tid + 256] = h4(src[tid + 256]);
        return;
    }
    int row = blk;
    const float4* xr = (const float4*)(x + (size_t)row * D);
    float4 v0 = xr[tid];
    float4 v1 = xr[tid + 256];
    float s  = v0.x + v0.y + v0.z + v0.w + v1.x + v1.y + v1.z + v1.w;
    float ss = v0.x*v0.x + v0.y*v0.y + v0.z*v0.z + v0.w*v0.w
             + v1.x*v1.x + v1.y*v1.y + v1.z*v1.z + v1.w*v1.w;
    #pragma unroll
    for (int o = 16; o; o >>= 1) {
        s  += __shfl_xor_sync(0xFFFFFFFFu, s, o);
        ss += __shfl_xor_sync(0xFFFFFFFFu, ss, o);
    }
    int wid = tid >> 5;
    if ((tid & 31) == 0) { redS[wid] = s; redQ[wid] = ss; }
    __syncthreads();
    float ts = 0.f, tq = 0.f;
    #pragma unroll
    for (int i = 0; i < 8; i++) { ts += redS[i]; tq += redQ[i]; }
    float mean = ts * (1.0f / D);
    float var  = tq * (1.0f / D) - mean * mean;
    float r = 1.0f / sqrtf(var + LN_EPS);

    const float4* wr = (const float4*)w;
    const float4* br = (const float4*)b;
    float4 w0 = wr[tid], w1 = wr[tid + 256];
    float4 b0 = br[tid], b1 = br[tid + 256];
    float4 o0, o1;
    o0.x = (v0.x - mean) * r * w0.x + b0.x;
    o0.y = (v0.y - mean) * r * w0.y + b0.y;
    o0.z = (v0.z - mean) * r * w0.z + b0.z;
    o0.w = (v0.w - mean) * r * w0.w + b0.w;
    o1.x = (v1.x - mean) * r * w1.x + b1.x;
    o1.y = (v1.y - mean) * r * w1.y + b1.y;
    o1.z = (v1.z - mean) * r * w1.z + b1.z;
    o1.w = (v1.w - mean) * r * w1.w + b1.w;

    uint2* arow = (uint2*)(g_Ah + (size_t)row * (D / 2));
    arow[tid] = h4(o0);
    arow[tid + 256] = h4(o1);
}

// ---------------- QKV GEMM via mma.sync fp16 m16n8k16 ------------------------
// q,k,v all written as packed fp16
__global__ __launch_bounds__(256, 2) void qkv_mma_kernel(const float* __restrict__ bq,
                                                         const float* __restrict__ bk,
                                                         const float* __restrict__ bv) {
    extern __shared__ __align__(128) char sm[];
    uint32_t sbase = smem_u32(sm);

    int tid = threadIdx.x;
    int lane = tid & 31;
    int wid = tid >> 5;
    int warp_m = wid >> 2;
    int warp_n = wid & 3;
    int bx = blockIdx.x;
    int by = blockIdx.y;
    int bz = blockIdx.z;

    const float* bias = (bz == 0) ? bq : (bz == 1) ? bk : bv;
    uint32_t* Ch = (bz == 0) ? g_qh : (bz == 1) ? g_kh : g_vh;
    const char* Abase = (const char*)g_Ah;                                     // row stride 4096 B
    const char* Bbase = (const char*)(g_Wh + (size_t)bz * ((size_t)D * D / 2)); // row stride 4096 B

    auto load_stage = [&](int st, int j) {
        size_t koff = (size_t)j * 128;
        uint32_t sA = sbase + st * GSTAGE_BYTES;
        uint32_t sB = sA + 16384;
        #pragma unroll
        for (int i = 0; i < 4; i++) {
            int idx = tid + i * 256;
            int row = idx >> 3;
            int c16 = idx & 7;
            uint32_t dst = sA + row * 128 + ((c16 ^ (row & 7)) << 4);
            cp16(dst, Abase + (size_t)(by * GBM + row) * 4096 + koff + c16 * 16);
        }
        #pragma unroll
        for (int i = 0; i < 4; i++) {
            int idx = tid + i * 256;
            int row = idx >> 3;
            int c16 = idx & 7;
            uint32_t dst = sB + row * 128 + ((c16 ^ (row & 7)) << 4);
            cp16(dst, Bbase + (size_t)(bx * GBN + row) * 4096 + koff + c16 * 16);
        }
    };

    float acc[4][4][4];
    #pragma unroll
    for (int mf = 0; mf < 4; mf++)
        #pragma unroll
        for (int nf = 0; nf < 4; nf++)
            #pragma unroll
            for (int q = 0; q < 4; q++) acc[mf][nf][q] = 0.f;

    load_stage(0, 0);
    cp_commit();
    load_stage(1, 1);
    cp_commit();

    int arow_off = warp_m * 64 + (lane & 15);
    int brow_off = warp_n * 32 + (lane & 15);
    int khalf = lane >> 4;
    int swz_x = lane & 7;

    for (int it = 0; it < KITERS; it++) {
        cp_wait<1>();
        __syncthreads();
        if (it + 2 < KITERS) load_stage((it + 2) % GSTAGES, it + 2);
        cp_commit();

        uint32_t sA = sbase + (it % GSTAGES) * GSTAGE_BYTES;
        uint32_t sB = sA + 16384;

        #pragma unroll
        for (int ks = 0; ks < 4; ks++) {
            uint32_t swz = (uint32_t)(((ks * 2 + khalf) ^ swz_x) << 4);
            uint32_t a[4][4];
            uint32_t bf[4][2];
            #pragma unroll
            for (int mf = 0; mf < 4; mf++) {
                uint32_t addr = sA + (uint32_t)(arow_off + mf * 16) * 128 + swz;
                LDSM4(a[mf][0], a[mf][1], a[mf][2], a[mf][3], addr);
            }
            #pragma unroll
            for (int nf2 = 0; nf2 < 2; nf2++) {
                uint32_t r0, r1, r2, r3;
                uint32_t addr = sB + (uint32_t)(brow_off + nf2 * 16) * 128 + swz;
                LDSM4(r0, r1, r2, r3, addr);
                bf[nf2 * 2 + 0][0] = r0; bf[nf2 * 2 + 1][0] = r1;
                bf[nf2 * 2 + 0][1] = r2; bf[nf2 * 2 + 1][1] = r3;
            }
            #pragma unroll
            for (int mf = 0; mf < 4; mf++)
                #pragma unroll
                for (int nf = 0; nf < 4; nf++)
                    MMA16816(acc[mf][nf], a[mf], bf[nf][0], bf[nf][1]);
        }
        __syncthreads();
    }

    // epilogue: bias + store packed fp16
    int row_base = by * GBM + warp_m * 64 + (lane >> 2);
    int col_base = bx * GBN + warp_n * 32 + 2 * (lane & 3);   // even
    #pragma unroll
    for (int nf = 0; nf < 4; nf++) {
        int c = col_base + nf * 8;
        float b0 = bias[c], b1 = bias[c + 1];
        #pragma unroll
        for (int mf = 0; mf < 4; mf++) {
            int r0 = row_base + mf * 16;
            Ch[(size_t)r0 * (D / 2) + (c >> 1)] =
                f16x2(acc[mf][nf][0] + b0, acc[mf][nf][1] + b1);
            Ch[(size_t)(r0 + 8) * (D / 2) + (c >> 1)] =
                f16x2(acc[mf][nf][2] + b0, acc[mf][nf][3] + b1);
        }
    }
}

// ---------------- scores via fp16 mma ----------------------------------------
__global__ __launch_bounds__(128) void scores_mma_kernel() {
    __shared__ __align__(128) char sm[3 * 16384];
    uint32_t sbase = smem_u32(sm);
    int ks = blockIdx.x;
    int b = blockIdx.y;
    int tid = threadIdx.x;
    int lane = tid & 31;
    int w = tid >> 5;

    const char* Qb = (const char*)g_qh + (size_t)b * NA * 4096 + (size_t)ks * (SCORE_KCHUNK * 2);
    const char* Kb = (const char*)g_kh + (size_t)b * NA * 4096 + (size_t)ks * (SCORE_KCHUNK * 2);

    auto load_stage = [&](int st, int j) {
        size_t koff = (size_t)j * 128;
        uint32_t sQ = sbase + st * 16384;
        uint32_t sK = sQ + 8192;
        #pragma unroll
        for (int i = 0; i < 4; i++) {
            int idx = tid + i * 128;
            int row = idx >> 3;
            int c16 = idx & 7;
            uint32_t dst = sQ + row * 128 + ((c16 ^ (row & 7)) << 4);
            cp16(dst, Qb + (size_t)row * 4096 + koff + c16 * 16);
        }
        #pragma unroll
        for (int i = 0; i < 4; i++) {
            int idx = tid + i * 128;
            int row = idx >> 3;
            int c16 = idx & 7;
            uint32_t dst = sK + row * 128 + ((c16 ^ (row & 7)) << 4);
            cp16(dst, Kb + (size_t)row * 4096 + koff + c16 * 16);
        }
    };

    float acc[8][4];
    #pragma unroll
    for (int nf = 0; nf < 8; nf++)
        #pragma unroll
        for (int q = 0; q < 4; q++) acc[nf][q] = 0.f;

    load_stage(0, 0);
    cp_commit();
    load_stage(1, 1);
    cp_commit();

    int arow_off = w * 16 + (lane & 15);
    int brow_off = lane & 15;
    int khalf = lane >> 4;
    int swz_x = lane & 7;
    const int NIT = SCORE_KCHUNK / 64;     // 8

    for (int it = 0; it < NIT; it++) {
        cp_wait<1>();
        __syncthreads();
        if (it + 2 < NIT) load_stage((it + 2) % 3, it + 2);
        cp_commit();

        uint32_t sQ = sbase + (it % 3) * 16384;
        uint32_t sK = sQ + 8192;

        #pragma unroll
        for (int g = 0; g < 4; g++) {
            uint32_t swz = (uint32_t)(((g * 2 + khalf) ^ swz_x) << 4);
            uint32_t a[4];
            LDSM4(a[0], a[1], a[2], a[3], sQ + (uint32_t)arow_off * 128 + swz);
            uint32_t bf[8][2];
            #pragma unroll
            for (int nf2 = 0; nf2 < 4; nf2++) {
                uint32_t r0, r1, r2, r3;
                LDSM4(r0, r1, r2, r3, sK + (uint32_t)(brow_off + nf2 * 16) * 128 + swz);
                bf[nf2 * 2 + 0][0] = r0; bf[nf2 * 2 + 1][0] = r1;
                bf[nf2 * 2 + 0][1] = r2; bf[nf2 * 2 + 1][1] = r3;
            }
            #pragma unroll
            for (int nf = 0; nf < 8; nf++)
                MMA16816(acc[nf], a, bf[nf][0], bf[nf][1]);
        }
        __syncthreads();
    }

    float* dst = g_spart + ((size_t)ks * BATCH + b) * 4096;
    int rrow = w * 16 + (lane >> 2);
    int ccol = 2 * (lane & 3);
    #pragma unroll
    for (int nf = 0; nf < 8; nf++) {
        int c = nf * 8 + ccol;
        dst[rrow * 64 + c] = acc[nf][0];
        dst[rrow * 64 + c + 1] = acc[nf][1];
        dst[(rrow + 8) * 64 + c] = acc[nf][2];
        dst[(rrow + 8) * 64 + c + 1] = acc[nf][3];
    }
}

// ---------------- Sinkhorn in log2 domain, max-free -------------------------
// la2 = logits * log2(e)/scale; row/col: la2 -= lg2(sum(ex2(la2)))
__global__ __launch_bounds__(1024) void sinkhorn_kernel(float* __restrict__ attn_out) {
    int b = blockIdx.x;
    __shared__ float m[64][65];
    int tid = threadIdx.x;
    // (1/(sqrt(2048)*TEMP)) * log2(e)
    const float invS2 = (1.0f / 45.254833995939045f) * 1.4426950408889634f;
    const float* p0 = g_spart + (size_t)b * 4096;
    const size_t pstride = (size_t)BATCH * 4096;
    for (int i = tid; i < 4096; i += 1024) {
        float v = p0[i] + p0[i + pstride] + p0[i + 2 * pstride] + p0[i + 3 * pstride];
        m[i >> 6][i & 63] = v * invS2;
    }
    __syncthreads();
    int w = tid >> 5, lane = tid & 31;
    for (int it = 0; it < SINKHORN_ITERS; it++) {
        // row normalize (over last index), base-2, no max subtraction
        #pragma unroll
        for (int rr = 0; rr < 2; rr++) {
            int r = w * 2 + rr;
            float x0 = m[r][lane], x1 = m[r][lane + 32];
            float s = ex2(x0) + ex2(x1);
            #pragma unroll
            for (int o = 16; o; o >>= 1) s += __shfl_xor_sync(0xFFFFFFFFu, s, o);
            float lse = lg2(s);
            m[r][lane] = x0 - lse;
            m[r][lane + 32] = x1 - lse;
        }
        __syncthreads();
        // col normalize (over first index)
        #pragma unroll
        for (int cc = 0; cc < 2; cc++) {
            int c = w * 2 + cc;
            float x0 = m[lane][c], x1 = m[lane + 32][c];
            float s = ex2(x0) + ex2(x1);
            #pragma unroll
            for (int o = 16; o; o >>= 1) s += __shfl_xor_sync(0xFFFFFFFFu, s, o);
            float lse = lg2(s);
            m[lane][c] = x0 - lse;
            m[lane + 32][c] = x1 - lse;
        }
        __syncthreads();
    }
    for (int i = tid; i < 4096; i += 1024) {
        float e = ex2(m[i >> 6][i & 63]);
        g_attn[(size_t)b * 4096 + i] = e;
        if (attn_out) attn_out[(size_t)b * 4096 + i] = e;
    }
}

// ---------------- attended = attn @ V(fp16), fused mix with fp16 normed ------
__global__ __launch_bounds__(256) void attended_kernel() {
    int d0 = blockIdx.x * 128;
    int b = blockIdx.y;
    __shared__ float attn_s[64][64];
    __shared__ float4 Vs[64][32];
    int tid = threadIdx.x;
    const float* ab = g_attn + (size_t)b * 4096;
    for (int i = tid; i < 4096; i += 256) attn_s[i >> 6][i & 63] = ab[i];
    const uint2* Vb = (const uint2*)g_vh;    // row = (b*64+m): index row*(D/4) + d/4
    {
        int r = tid >> 5;
        int c = tid & 31;
        #pragma unroll
        for (int p = 0; p < 8; p++) {
            int row = b * 64 + r + p * 8;
            uint2 vh = Vb[(size_t)row * (D / 4) + (d0 >> 2) + c];
            Vs[r + p * 8][c] = h4f4(vh);
        }
    }
    __syncthreads();
    int tx = tid & 31, ty = tid >> 5;
    float4 acc[8];
    #pragma unroll
    for (int i = 0; i < 8; i++) acc[i] = make_float4(0.f, 0.f, 0.f, 0.f);
    for (int mm = 0; mm < 64; mm++) {
        float4 v4 = Vs[mm][tx];
        #pragma unroll
        for (int i = 0; i < 8; i++) {
            float a = attn_s[ty * 8 + i][mm];
            acc[i].x += a * v4.x;
            acc[i].y += a * v4.y;
            acc[i].z += a * v4.z;
            acc[i].w += a * v4.w;
        }
    }
    const uint2* Ab = (const uint2*)g_Ah;
    #pragma unroll
    for (int i = 0; i < 8; i++) {
        int n = ty * 8 + i;
        int row = b * 64 + n;
        float4 nm = h4f4(Ab[(size_t)row * (D / 4) + (d0 >> 2) + tx]);
        size_t off = (size_t)row * D + d0 + tx * 4;
        float4 o;
        o.x = ID_PRESERVE * nm.x + (1.0f - ID_PRESERVE) * acc[i].x;
        o.y = ID_PRESERVE * nm.y + (1.0f - ID_PRESERVE) * acc[i].y;
        o.z = ID_PRESERVE * nm.z + (1.0f - ID_PRESERVE) * acc[i].z;
        o.w = ID_PRESERVE * nm.w + (1.0f - ID_PRESERVE) * acc[i].w;
        *(float4*)(g_mixed + off) = o;
    }
}

// ---------------- epilogue ---------------------------------------------------
__global__ __launch_bounds__(256) void epilogue_kernel(const float* __restrict__ x,
                                                       const float* __restrict__ biases,
                                                       const float* __restrict__ scales,
                                                       float* __restrict__ out) {
    __shared__ float red[8];
    int row = blockIdx.x;
    int n = row & 63;
    int tid = threadIdx.x;
    float sc = scales[n];
    const float4* mr = (const float4*)(g_mixed + (size_t)row * D);
    const float4* br = (const float4*)(biases + (size_t)n * D);
    float4 m0 = mr[tid], m1 = mr[tid + 256];
    float4 b0 = br[tid], b1 = br[tid + 256];
    float4 s0, s1;
    s0.x = (m0.x + b0.x) * sc; s0.y = (m0.y + b0.y) * sc;
    s0.z = (m0.z + b0.z) * sc; s0.w = (m0.w + b0.w) * sc;
    s1.x = (m1.x + b1.x) * sc; s1.y = (m1.y + b1.y) * sc;
    s1.z = (m1.z + b1.z) * sc; s1.w = (m1.w + b1.w) * sc;
    float ss = s0.x*s0.x + s0.y*s0.y + s0.z*s0.z + s0.w*s0.w
             + s1.x*s1.x + s1.y*s1.y + s1.z*s1.z + s1.w*s1.w;
    #pragma unroll
    for (int o = 16; o; o >>= 1) ss += __shfl_xor_sync(0xFFFFFFFFu, ss, o);
    if ((tid & 31) == 0) red[tid >> 5] = ss;
    __syncthreads();
    float tot = 0.f;
    #pragma unroll
    for (int i = 0; i < 8; i++) tot += red[i];
    float norm = sqrtf(tot);
    float inv = 1.0f / fmaxf(1.0f, norm / SIGNAL_BOUND);
    const float4* xr = (const float4*)(x + (size_t)row * D);
    float4 x0 = xr[tid], x1 = xr[tid + 256];
    float4 o0, o1;
    o0.x = x0.x + s0.x * inv; o0.y = x0.y + s0.y * inv;
    o0.z = x0.z + s0.z * inv; o0.w = x0.w + s0.w * inv;
    o1.x = x1.x + s1.x * inv; o1.y = x1.y + s1.y * inv;
    o1.z = x1.z + s1.z * inv; o1.w = x1.w + s1.w * inv;
    float4* outr = (float4*)(out + (size_t)row * D);
    outr[tid] = o0;
    outr[tid + 256] = o1;
}

// ---------------- launch -----------------------------------------------------
extern "C" void kernel_launch(void* const* d_in, const int* in_sizes, int n_in,
                              void* d_out, int out_size) {
    const float* agent_states  = (const float*)d_in[0];
    const float* ln_w          = (const float*)d_in[1];
    const float* ln_b          = (const float*)d_in[2];
    const float* wq            = (const float*)d_in[3];
    const float* bq            = (const float*)d_in[4];
    const float* wk            = (const float*)d_in[5];
    const float* bk            = (const float*)d_in[6];
    const float* wv            = (const float*)d_in[7];
    const float* bv            = (const float*)d_in[8];
    const float* agent_biases  = (const float*)d_in[9];
    const float* scale_factors = (const float*)d_in[10];
    float* out = (float*)d_out;
    float* attn_out = (out_size >= ROWS * D + BATCH * NA * NA) ? (out + (size_t)ROWS * D)
                                                               : nullptr;

    const int DYN_SMEM = GSTAGES * GSTAGE_BYTES;   // 96 KB
    cudaFuncSetAttribute(qkv_mma_kernel, cudaFuncAttributeMaxDynamicSharedMemorySize, DYN_SMEM);

    prep_kernel<<<ROWS + 3 * D, 256>>>(agent_states, ln_w, ln_b, wq, wk, wv);
    qkv_mma_kernel<<<dim3(D / GBN, ROWS / GBM, 3), 256, DYN_SMEM>>>(bq, bk, bv);
    scores_mma_kernel<<<dim3(SCORE_KSPLIT, BATCH), 128>>>();
    sinkhorn_kernel<<<BATCH, 1024>>>(attn_out);
    attended_kernel<<<dim3(16, BATCH), 256>>>();
    epilogue_kernel<<<ROWS, 256>>>(agent_states, agent_biases, scale_factors, out);
}

// round 17
// speedup vs baseline: 2.7500x; 1.0193x over previous
#include <cuda_runtime.h>
#include <math.h>
#include <stdint.h>

#define D 2048
#define NA 64
#define BATCH 64
#define ROWS (BATCH * NA)        // 4096
#define LN_EPS 1e-5f
#define ID_PRESERVE 0.1f
#define SIGNAL_BOUND 1.0f
#define SINKHORN_ITERS 50

// GEMM: CTA 128x128, fp16 single pass K=2048, BK=64 fp16 (128B rows), 3-stage
#define GBM 128
#define GBN 128
#define KITERS 32                // 2048 / 64
#define GSTAGES 3
#define GSTAGE_BYTES 32768       // A 16KB + B 16KB (128 rows x 128B each)

#define SCORE_KSPLIT 4
#define SCORE_KCHUNK (D / SCORE_KSPLIT)   // 512 elems

// ---------------- scratch (device globals; no allocation allowed) ----------
__device__ float g_mixed[ROWS * D];
__device__ float g_spart[SCORE_KSPLIT * BATCH * NA * NA];
__device__ float g_attn[BATCH * NA * NA];
// fp16 operands stored as packed u32 pairs (no cuda_fp16.h — triggers infra failure)
__device__ uint32_t g_Ah[(size_t)ROWS * D / 2];          // fp16(normed) [4096, 2048]
__device__ uint32_t g_Wh[3ull * D * D / 2];              // 3 x [2048, 2048] fp16
__device__ uint32_t g_qh[(size_t)ROWS * D / 2];          // q in fp16
__device__ uint32_t g_kh[(size_t)ROWS * D / 2];          // k in fp16
__device__ uint32_t g_vh[(size_t)ROWS * D / 2];          // v in fp16

// ---------------- PTX helpers ------------------------------------------------
__device__ __forceinline__ uint32_t smem_u32(const void* p) {
    uint32_t a;
    asm("{ .reg .u64 t; cvta.to.shared.u64 t, %1; cvt.u32.u64 %0, t; }" : "=r"(a) : "l"(p));
    return a;
}
__device__ __forceinline__ void cp16(uint32_t dst, const void* src) {
    asm volatile("cp.async.cg.shared.global [%0], [%1], 16;" :: "r"(dst), "l"(src));
}
__device__ __forceinline__ void cp_commit() { asm volatile("cp.async.commit_group;" ::: "memory"); }
template <int N>
__device__ __forceinline__ void cp_wait() { asm volatile("cp.async.wait_group %0;" :: "n"(N) : "memory"); }

#define LDSM4(r0, r1, r2, r3, addr) \
    asm volatile("ldmatrix.sync.aligned.m8n8.x4.shared.b16 {%0,%1,%2,%3}, [%4];" \
                 : "=r"(r0), "=r"(r1), "=r"(r2), "=r"(r3) : "r"(addr))

#define MMA16816(acc, a, b0r, b1r) \
    asm volatile( \
        "mma.sync.aligned.m16n8k16.row.col.f32.f16.f16.f32 " \
        "{%0,%1,%2,%3}, {%4,%5,%6,%7}, {%8,%9}, {%0,%1,%2,%3};" \
        : "+f"((acc)[0]), "+f"((acc)[1]), "+f"((acc)[2]), "+f"((acc)[3]) \
        : "r"((a)[0]), "r"((a)[1]), "r"((a)[2]), "r"((a)[3]), \
          "r"(b0r), "r"(b1r))

// pack two fp32 -> fp16x2 in a b32 register (pure PTX, no half headers)
__device__ __forceinline__ uint32_t f16x2(float lo, float hi) {
    uint32_t r;
    asm("{ .reg .f16 a, b;\n\t"
        "cvt.rn.f16.f32 a, %1;\n\t"
        "cvt.rn.f16.f32 b, %2;\n\t"
        "mov.b32 %0, {a, b}; }"
        : "=r"(r) : "f"(lo), "f"(hi));
    return r;
}
__device__ __forceinline__ uint2 h4(float4 v) {
    uint2 u;
    u.x = f16x2(v.x, v.y);
    u.y = f16x2(v.z, v.w);
    return u;
}
// unpack fp16x2 -> two fp32
__device__ __forceinline__ float2 h2f2(uint32_t h) {
    float2 f;
    asm("{ .reg .f16 lo, hi;\n\t"
        "mov.b32 {lo, hi}, %2;\n\t"
        "cvt.f32.f16 %0, lo;\n\t"
        "cvt.f32.f16 %1, hi; }"
        : "=f"(f.x), "=f"(f.y) : "r"(h));
    return f;
}
__device__ __forceinline__ float4 h4f4(uint2 u) {
    float2 a = h2f2(u.x), b = h2f2(u.y);
    return make_float4(a.x, a.y, b.x, b.y);
}
// base-2 exp and fast reciprocal via MUFU
__device__ __forceinline__ float ex2(float x) {
    float y;
    asm("ex2.approx.f32 %0, %1;" : "=f"(y) : "f"(x));
    return y;
}
__device__ __forceinline__ float frcp(float x) {
    float y;
    asm("rcp.approx.f32 %0, %1;" : "=f"(y) : "f"(x));
    return y;
}

// ---------------- prep: LayerNorm->fp16 A, plus fp16 W convert ---------------
// grid: [0, ROWS) = ln rows; [ROWS, ROWS+3*D) = weight rows
__global__ __launch_bounds__(256) void prep_kernel(const float* __restrict__ x,
                                                   const float* __restrict__ w,
                                                   const float* __restrict__ b,
                                                   const float* __restrict__ wq,
                                                   const float* __restrict__ wk,
                                                   const float* __restrict__ wv) {
    __shared__ float redS[8], redQ[8];
    int blk = blockIdx.x;
    int tid = threadIdx.x;
    if (blk >= ROWS) {
        int t = blk - ROWS;
        int wsel = t >> 11;                // t / D
        int j = t & (D - 1);               // t % D
        const float* W = (wsel == 0) ? wq : (wsel == 1) ? wk : wv;
        uint2* dst = (uint2*)(g_Wh + (size_t)wsel * ((size_t)D * D / 2) + (size_t)j * (D / 2));
        const float4* src = (const float4*)(W + (size_t)j * D);
        dst[tid] = h4(src[tid]);
        dst[tid + 256] = h4(src[tid + 256]);
        return;
    }
    int row = blk;
    const float4* xr = (const float4*)(x + (size_t)row * D);
    float4 v0 = xr[tid];
    float4 v1 = xr[tid + 256];
    float s  = v0.x + v0.y + v0.z + v0.w + v1.x + v1.y + v1.z + v1.w;
    float ss = v0.x*v0.x + v0.y*v0.y + v0.z*v0.z + v0.w*v0.w
             + v1.x*v1.x + v1.y*v1.y + v1.z*v1.z + v1.w*v1.w;
    #pragma unroll
    for (int o = 16; o; o >>= 1) {
        s  += __shfl_xor_sync(0xFFFFFFFFu, s, o);
        ss += __shfl_xor_sync(0xFFFFFFFFu, ss, o);
    }
    int wid = tid >> 5;
    if ((tid & 31) == 0) { redS[wid] = s; redQ[wid] = ss; }
    __syncthreads();
    float ts = 0.f, tq = 0.f;
    #pragma unroll
    for (int i = 0; i < 8; i++) { ts += redS[i]; tq += redQ[i]; }
    float mean = ts * (1.0f / D);
    float var  = tq * (1.0f / D) - mean * mean;
    float r = 1.0f / sqrtf(var + LN_EPS);

    const float4* wr = (const float4*)w;
    const float4* br = (const float4*)b;
    float4 w0 = wr[tid], w1 = wr[tid + 256];
    float4 b0 = br[tid], b1 = br[tid + 256];
    float4 o0, o1;
    o0.x = (v0.x - mean) * r * w0.x + b0.x;
    o0.y = (v0.y - mean) * r * w0.y + b0.y;
    o0.z = (v0.z - mean) * r * w0.z + b0.z;
    o0.w = (v0.w - mean) * r * w0.w + b0.w;
    o1.x = (v1.x - mean) * r * w1.x + b1.x;
    o1.y = (v1.y - mean) * r * w1.y + b1.y;
    o1.z = (v1.z - mean) * r * w1.z + b1.z;
    o1.w = (v1.w - mean) * r * w1.w + b1.w;

    uint2* arow = (uint2*)(g_Ah + (size_t)row * (D / 2));
    arow[tid] = h4(o0);
    arow[tid + 256] = h4(o1);
}

// ---------------- QKV GEMM via mma.sync fp16 m16n8k16 ------------------------
// q,k,v all written as packed fp16
__global__ __launch_bounds__(256, 2) void qkv_mma_kernel(const float* __restrict__ bq,
                                                         const float* __restrict__ bk,
                                                         const float* __restrict__ bv) {
    extern __shared__ __align__(128) char sm[];
    uint32_t sbase = smem_u32(sm);

    int tid = threadIdx.x;
    int lane = tid & 31;
    int wid = tid >> 5;
    int warp_m = wid >> 2;
    int warp_n = wid & 3;
    int bx = blockIdx.x;
    int by = blockIdx.y;
    int bz = blockIdx.z;

    const float* bias = (bz == 0) ? bq : (bz == 1) ? bk : bv;
    uint32_t* Ch = (bz == 0) ? g_qh : (bz == 1) ? g_kh : g_vh;
    const char* Abase = (const char*)g_Ah;                                     // row stride 4096 B
    const char* Bbase = (const char*)(g_Wh + (size_t)bz * ((size_t)D * D / 2)); // row stride 4096 B

    auto load_stage = [&](int st, int j) {
        size_t koff = (size_t)j * 128;
        uint32_t sA = sbase + st * GSTAGE_BYTES;
        uint32_t sB = sA + 16384;
        #pragma unroll
        for (int i = 0; i < 4; i++) {
            int idx = tid + i * 256;
            int row = idx >> 3;
            int c16 = idx & 7;
            uint32_t dst = sA + row * 128 + ((c16 ^ (row & 7)) << 4);
            cp16(dst, Abase + (size_t)(by * GBM + row) * 4096 + koff + c16 * 16);
        }
        #pragma unroll
        for (int i = 0; i < 4; i++) {
            int idx = tid + i * 256;
            int row = idx >> 3;
            int c16 = idx & 7;
            uint32_t dst = sB + row * 128 + ((c16 ^ (row & 7)) << 4);
            cp16(dst, Bbase + (size_t)(bx * GBN + row) * 4096 + koff + c16 * 16);
        }
    };

    float acc[4][4][4];
    #pragma unroll
    for (int mf = 0; mf < 4; mf++)
        #pragma unroll
        for (int nf = 0; nf < 4; nf++)
            #pragma unroll
            for (int q = 0; q < 4; q++) acc[mf][nf][q] = 0.f;

    load_stage(0, 0);
    cp_commit();
    load_stage(1, 1);
    cp_commit();

    int arow_off = warp_m * 64 + (lane & 15);
    int brow_off = warp_n * 32 + (lane & 15);
    int khalf = lane >> 4;
    int swz_x = lane & 7;

    for (int it = 0; it < KITERS; it++) {
        cp_wait<1>();
        __syncthreads();
        if (it + 2 < KITERS) load_stage((it + 2) % GSTAGES, it + 2);
        cp_commit();

        uint32_t sA = sbase + (it % GSTAGES) * GSTAGE_BYTES;
        uint32_t sB = sA + 16384;

        #pragma unroll
        for (int ks = 0; ks < 4; ks++) {
            uint32_t swz = (uint32_t)(((ks * 2 + khalf) ^ swz_x) << 4);
            uint32_t a[4][4];
            uint32_t bf[4][2];
            #pragma unroll
            for (int mf = 0; mf < 4; mf++) {
                uint32_t addr = sA + (uint32_t)(arow_off + mf * 16) * 128 + swz;
                LDSM4(a[mf][0], a[mf][1], a[mf][2], a[mf][3], addr);
            }
            #pragma unroll
            for (int nf2 = 0; nf2 < 2; nf2++) {
                uint32_t r0, r1, r2, r3;
                uint32_t addr = sB + (uint32_t)(brow_off + nf2 * 16) * 128 + swz;
                LDSM4(r0, r1, r2, r3, addr);
                bf[nf2 * 2 + 0][0] = r0; bf[nf2 * 2 + 1][0] = r1;
                bf[nf2 * 2 + 0][1] = r2; bf[nf2 * 2 + 1][1] = r3;
            }
            #pragma unroll
            for (int mf = 0; mf < 4; mf++)
                #pragma unroll
                for (int nf = 0; nf < 4; nf++)
                    MMA16816(acc[mf][nf], a[mf], bf[nf][0], bf[nf][1]);
        }
        __syncthreads();
    }

    // epilogue: bias + store packed fp16
    int row_base = by * GBM + warp_m * 64 + (lane >> 2);
    int col_base = bx * GBN + warp_n * 32 + 2 * (lane & 3);   // even
    #pragma unroll
    for (int nf = 0; nf < 4; nf++) {
        int c = col_base + nf * 8;
        float b0 = bias[c], b1 = bias[c + 1];
        #pragma unroll
        for (int mf = 0; mf < 4; mf++) {
            int r0 = row_base + mf * 16;
            Ch[(size_t)r0 * (D / 2) + (c >> 1)] =
                f16x2(acc[mf][nf][0] + b0, acc[mf][nf][1] + b1);
            Ch[(size_t)(r0 + 8) * (D / 2) + (c >> 1)] =
                f16x2(acc[mf][nf][2] + b0, acc[mf][nf][3] + b1);
        }
    }
}

// ---------------- scores via fp16 mma ----------------------------------------
__global__ __launch_bounds__(128) void scores_mma_kernel() {
    __shared__ __align__(128) char sm[3 * 16384];
    uint32_t sbase = smem_u32(sm);
    int ks = blockIdx.x;
    int b = blockIdx.y;
    int tid = threadIdx.x;
    int lane = tid & 31;
    int w = tid >> 5;

    const char* Qb = (const char*)g_qh + (size_t)b * NA * 4096 + (size_t)ks * (SCORE_KCHUNK * 2);
    const char* Kb = (const char*)g_kh + (size_t)b * NA * 4096 + (size_t)ks * (SCORE_KCHUNK * 2);

    auto load_stage = [&](int st, int j) {
        size_t koff = (size_t)j * 128;
        uint32_t sQ = sbase + st * 16384;
        uint32_t sK = sQ + 8192;
        #pragma unroll
        for (int i = 0; i < 4; i++) {
            int idx = tid + i * 128;
            int row = idx >> 3;
            int c16 = idx & 7;
            uint32_t dst = sQ + row * 128 + ((c16 ^ (row & 7)) << 4);
            cp16(dst, Qb + (size_t)row * 4096 + koff + c16 * 16);
        }
        #pragma unroll
        for (int i = 0; i < 4; i++) {
            int idx = tid + i * 128;
            int row = idx >> 3;
            int c16 = idx & 7;
            uint32_t dst = sK + row * 128 + ((c16 ^ (row & 7)) << 4);
            cp16(dst, Kb + (size_t)row * 4096 + koff + c16 * 16);
        }
    };

    float acc[8][4];
    #pragma unroll
    for (int nf = 0; nf < 8; nf++)
        #pragma unroll
        for (int q = 0; q < 4; q++) acc[nf][q] = 0.f;

    load_stage(0, 0);
    cp_commit();
    load_stage(1, 1);
    cp_commit();

    int arow_off = w * 16 + (lane & 15);
    int brow_off = lane & 15;
    int khalf = lane >> 4;
    int swz_x = lane & 7;
    const int NIT = SCORE_KCHUNK / 64;     // 8

    for (int it = 0; it < NIT; it++) {
        cp_wait<1>();
        __syncthreads();
        if (it + 2 < NIT) load_stage((it + 2) % 3, it + 2);
        cp_commit();

        uint32_t sQ = sbase + (it % 3) * 16384;
        uint32_t sK = sQ + 8192;

        #pragma unroll
        for (int g = 0; g < 4; g++) {
            uint32_t swz = (uint32_t)(((g * 2 + khalf) ^ swz_x) << 4);
            uint32_t a[4];
            LDSM4(a[0], a[1], a[2], a[3], sQ + (uint32_t)arow_off * 128 + swz);
            uint32_t bf[8][2];
            #pragma unroll
            for (int nf2 = 0; nf2 < 4; nf2++) {
                uint32_t r0, r1, r2, r3;
                LDSM4(r0, r1, r2, r3, sK + (uint32_t)(brow_off + nf2 * 16) * 128 + swz);
                bf[nf2 * 2 + 0][0] = r0; bf[nf2 * 2 + 1][0] = r1;
                bf[nf2 * 2 + 0][1] = r2; bf[nf2 * 2 + 1][1] = r3;
            }
            #pragma unroll
            for (int nf = 0; nf < 8; nf++)
                MMA16816(acc[nf], a, bf[nf][0], bf[nf][1]);
        }
        __syncthreads();
    }

    float* dst = g_spart + ((size_t)ks * BATCH + b) * 4096;
    int rrow = w * 16 + (lane >> 2);
    int ccol = 2 * (lane & 3);
    #pragma unroll
    for (int nf = 0; nf < 8; nf++) {
        int c = nf * 8 + ccol;
        dst[rrow * 64 + c] = acc[nf][0];
        dst[rrow * 64 + c + 1] = acc[nf][1];
        dst[(rrow + 8) * 64 + c] = acc[nf][2];
        dst[(rrow + 8) * 64 + c + 1] = acc[nf][3];
    }
}

// ---------------- Sinkhorn, linear domain (exp once, divide per phase) -------
__global__ __launch_bounds__(1024) void sinkhorn_kernel(float* __restrict__ attn_out) {
    int b = blockIdx.x;
    __shared__ float m[64][65];
    int tid = threadIdx.x;
    // (1/(sqrt(2048)*TEMP)) * log2(e)
    const float invS2 = (1.0f / 45.254833995939045f) * 1.4426950408889634f;
    const float* p0 = g_spart + (size_t)b * 4096;
    const size_t pstride = (size_t)BATCH * 4096;
    for (int i = tid; i < 4096; i += 1024) {
        float v = p0[i] + p0[i + pstride] + p0[i + 2 * pstride] + p0[i + 3 * pstride];
        m[i >> 6][i & 63] = ex2(v * invS2);
    }
    __syncthreads();
    int w = tid >> 5, lane = tid & 31;
    for (int it = 0; it < SINKHORN_ITERS; it++) {
        // row normalize: divide by row sum
        #pragma unroll
        for (int rr = 0; rr < 2; rr++) {
            int r = w * 2 + rr;
            float x0 = m[r][lane], x1 = m[r][lane + 32];
            float s = x0 + x1;
            #pragma unroll
            for (int o = 16; o; o >>= 1) s += __shfl_xor_sync(0xFFFFFFFFu, s, o);
            float inv = frcp(s);
            m[r][lane] = x0 * inv;
            m[r][lane + 32] = x1 * inv;
        }
        __syncthreads();
        // col normalize: divide by col sum
        #pragma unroll
        for (int cc = 0; cc < 2; cc++) {
            int c = w * 2 + cc;
            float x0 = m[lane][c], x1 = m[lane + 32][c];
            float s = x0 + x1;
            #pragma unroll
            for (int o = 16; o; o >>= 1) s += __shfl_xor_sync(0xFFFFFFFFu, s, o);
            float inv = frcp(s);
            m[lane][c] = x0 * inv;
            m[lane + 32][c] = x1 * inv;
        }
        __syncthreads();
    }
    for (int i = tid; i < 4096; i += 1024) {
        float e = m[i >> 6][i & 63];
        g_attn[(size_t)b * 4096 + i] = e;
        if (attn_out) attn_out[(size_t)b * 4096 + i] = e;
    }
}

// ---------------- attended = attn @ V(fp16), fused mix with fp16 normed ------
__global__ __launch_bounds__(256) void attended_kernel() {
    int d0 = blockIdx.x * 128;
    int b = blockIdx.y;
    __shared__ float attn_s[64][64];
    __shared__ float4 Vs[64][32];
    int tid = threadIdx.x;
    const float* ab = g_attn + (size_t)b * 4096;
    for (int i = tid; i < 4096; i += 256) attn_s[i >> 6][i & 63] = ab[i];
    const uint2* Vb = (const uint2*)g_vh;    // row = (b*64+m): index row*(D/4) + d/4
    {
        int r = tid >> 5;
        int c = tid & 31;
        #pragma unroll
        for (int p = 0; p < 8; p++) {
            int row = b * 64 + r + p * 8;
            uint2 vh = Vb[(size_t)row * (D / 4) + (d0 >> 2) + c];
            Vs[r + p * 8][c] = h4f4(vh);
        }
    }
    __syncthreads();
    int tx = tid & 31, ty = tid >> 5;
    float4 acc[8];
    #pragma unroll
    for (int i = 0; i < 8; i++) acc[i] = make_float4(0.f, 0.f, 0.f, 0.f);
    for (int mm = 0; mm < 64; mm++) {
        float4 v4 = Vs[mm][tx];
        #pragma unroll
        for (int i = 0; i < 8; i++) {
            float a = attn_s[ty * 8 + i][mm];
            acc[i].x += a * v4.x;
            acc[i].y += a * v4.y;
            acc[i].z += a * v4.z;
            acc[i].w += a * v4.w;
        }
    }
    const uint2* Ab = (const uint2*)g_Ah;
    #pragma unroll
    for (int i = 0; i < 8; i++) {
        int n = ty * 8 + i;
        int row = b * 64 + n;
        float4 nm = h4f4(Ab[(size_t)row * (D / 4) + (d0 >> 2) + tx]);
        size_t off = (size_t)row * D + d0 + tx * 4;
        float4 o;
        o.x = ID_PRESERVE * nm.x + (1.0f - ID_PRESERVE) * acc[i].x;
        o.y = ID_PRESERVE * nm.y + (1.0f - ID_PRESERVE) * acc[i].y;
        o.z = ID_PRESERVE * nm.z + (1.0f - ID_PRESERVE) * acc[i].z;
        o.w = ID_PRESERVE * nm.w + (1.0f - ID_PRESERVE) * acc[i].w;
        *(float4*)(g_mixed + off) = o;
    }
}

// ---------------- epilogue ---------------------------------------------------
__global__ __launch_bounds__(256) void epilogue_kernel(const float* __restrict__ x,
                                                       const float* __restrict__ biases,
                                                       const float* __restrict__ scales,
                                                       float* __restrict__ out) {
    __shared__ float red[8];
    int row = blockIdx.x;
    int n = row & 63;
    int tid = threadIdx.x;
    float sc = scales[n];
    const float4* mr = (const float4*)(g_mixed + (size_t)row * D);
    const float4* br = (const float4*)(biases + (size_t)n * D);
    float4 m0 = mr[tid], m1 = mr[tid + 256];
    float4 b0 = br[tid], b1 = br[tid + 256];
    float4 s0, s1;
    s0.x = (m0.x + b0.x) * sc; s0.y = (m0.y + b0.y) * sc;
    s0.z = (m0.z + b0.z) * sc; s0.w = (m0.w + b0.w) * sc;
    s1.x = (m1.x + b1.x) * sc; s1.y = (m1.y + b1.y) * sc;
    s1.z = (m1.z + b1.z) * sc; s1.w = (m1.w + b1.w) * sc;
    float ss = s0.x*s0.x + s0.y*s0.y + s0.z*s0.z + s0.w*s0.w
             + s1.x*s1.x + s1.y*s1.y + s1.z*s1.z + s1.w*s1.w;
    #pragma unroll
    for (int o = 16; o; o >>= 1) ss += __shfl_xor_sync(0xFFFFFFFFu, ss, o);
    if ((tid & 31) == 0) red[tid >> 5] = ss;
    __syncthreads();
    float tot = 0.f;
    #pragma unroll
    for (int i = 0; i < 8; i++) tot += red[i];
    float norm = sqrtf(tot);
    float inv = 1.0f / fmaxf(1.0f, norm / SIGNAL_BOUND);
    const float4* xr = (const float4*)(x + (size_t)row * D);
    float4 x0 = xr[tid], x1 = xr[tid + 256];
    float4 o0, o1;
    o0.x = x0.x + s0.x * inv; o0.y = x0.y + s0.y * inv;
    o0.z = x0.z + s0.z * inv; o0.w = x0.w + s0.w * inv;
    o1.x = x1.x + s1.x * inv; o1.y = x1.y + s1.y * inv;
    o1.z = x1.z + s1.z * inv; o1.w = x1.w + s1.w * inv;
    float4* outr = (float4*)(out + (size_t)row * D);
    outr[tid] = o0;
    outr[tid + 256] = o1;
}

// ---------------- launch -----------------------------------------------------
extern "C" void kernel_launch(void* const* d_in, const int* in_sizes, int n_in,
                              void* d_out, int out_size) {
    const float* agent_states  = (const float*)d_in[0];
    const float* ln_w          = (const float*)d_in[1];
    const float* ln_b          = (const float*)d_in[2];
    const float* wq            = (const float*)d_in[3];
    const float* bq            = (const float*)d_in[4];
    const float* wk            = (const float*)d_in[5];
    const float* bk            = (const float*)d_in[6];
    const float* wv            = (const float*)d_in[7];
    const float* bv            = (const float*)d_in[8];
    const float* agent_biases  = (const float*)d_in[9];
    const float* scale_factors = (const float*)d_in[10];
    float* out = (float*)d_out;
    float* attn_out = (out_size >= ROWS * D + BATCH * NA * NA) ? (out + (size_t)ROWS * D)
                                                               : nullptr;

    const int DYN_SMEM = GSTAGES * GSTAGE_BYTES;   // 96 KB
    cudaFuncSetAttribute(qkv_mma_kernel, cudaFuncAttributeMaxDynamicSharedMemorySize, DYN_SMEM);

    prep_kernel<<<ROWS + 3 * D, 256>>>(agent_states, ln_w, ln_b, wq, wk, wv);
    qkv_mma_kernel<<<dim3(D / GBN, ROWS / GBM, 3), 256, DYN_SMEM>>>(bq, bk, bv);
    scores_mma_kernel<<<dim3(SCORE_KSPLIT, BATCH), 128>>>();
    sinkhorn_kernel<<<BATCH, 1024>>>(attn_out);
    attended_kernel<<<dim3(16, BATCH), 256>>>();
    epilogue_kernel<<<ROWS, 256>>>(agent_states, agent_biases, scale_factors, out);
}